// round 9
// baseline (speedup 1.0000x reference)
#include <cuda_runtime.h>
#include <cstdint>

#define DIM    1536
#define HEADS  12
#define HD     128
#define LTOK   3520
#define EPS    1e-6f
#define SCALE  0.08838834764831845f   // 1/sqrt(128)

// ---------------- scratch (no allocation allowed) ----------------
__device__ float g_q[LTOK * DIM];
__device__ float g_k[LTOK * DIM];
__device__ float g_v[LTOK * DIM];
__device__ float g_o[LTOK * DIM];

// ---------------- tf32 / ldmatrix helpers ----------------
__device__ __forceinline__ uint32_t f2tf(float f) {
    uint32_t u;
    asm("cvt.rna.tf32.f32 %0, %1;" : "=r"(u) : "f"(f));
    return u;
}

__device__ __forceinline__ void mma_tf32(float c[4],
    uint32_t a0, uint32_t a1, uint32_t a2, uint32_t a3,
    uint32_t b0, uint32_t b1)
{
    asm volatile(
        "mma.sync.aligned.m16n8k8.row.col.f32.tf32.tf32.f32 "
        "{%0,%1,%2,%3}, {%4,%5,%6,%7}, {%8,%9}, {%0,%1,%2,%3};\n"
        : "+f"(c[0]), "+f"(c[1]), "+f"(c[2]), "+f"(c[3])
        : "r"(a0), "r"(a1), "r"(a2), "r"(a3), "r"(b0), "r"(b1));
}

__device__ __forceinline__ void ldsm_x4(uint32_t& r0, uint32_t& r1,
                                        uint32_t& r2, uint32_t& r3, uint32_t addr)
{
    asm volatile("ldmatrix.sync.aligned.m8n8.x4.shared.b16 {%0,%1,%2,%3}, [%4];"
                 : "=r"(r0), "=r"(r1), "=r"(r2), "=r"(r3) : "r"(addr));
}
__device__ __forceinline__ uint32_t smem_addr(const void* p) {
    return (uint32_t)__cvta_generic_to_shared(p);
}

// ================= tf32 GEMM: C[M,N] = A[M,K] @ B[N,K]^T + bias ==========
// BM=BN=128, BK=32, 256 threads (8 warps as 2x4), warp tile 64x32.
// 2-stage double buffer in dynamic smem; fill free buffer at iter top.
#define GM_BM 128
#define GM_BN 128
#define GM_BK 32
#define GSTR  36   // row stride words (144B = 9*16B); %32=4 -> conflict-free LDSM/STS
#define GM_STAGE (GM_BM * GSTR)
#define GM_SMEM_BYTES (4 * GM_STAGE * 4)   // A0,A1,B0,B1

__device__ __forceinline__ void gemm_tile_tf32(
    const float* __restrict__ A, const float* __restrict__ B,
    const float* __restrict__ bias, float* __restrict__ C,
    int M, int N, int K, int m0, int n0,
    uint32_t* As, uint32_t* Bs)
{
    const int tid = threadIdx.x;
    const int lane = tid & 31;
    const int wid = tid >> 5;
    const int wm = wid >> 2;       // 0..1
    const int wn = wid & 3;        // 0..3

    // ldmatrix per-thread address components
    const int tr = lane & 7;
    const int mq = lane >> 3;
    const int a_row = tr + 8 * (mq & 1);
    const int a_ko  = 4 * (mq >> 1);
    const int b_row = tr + 8 * (mq >> 1);
    const int b_ko  = 4 * (mq & 1);

    // staging map: s = tid + i*256 -> row = s>>3 (0..127), kc = (s&7)*4
    int sr[4], kc4[4], arow[4], brow[4];
#pragma unroll
    for (int i = 0; i < 4; ++i) {
        int s = tid + i * 256;
        sr[i]  = s >> 3;
        kc4[i] = (s & 7) * 4;
        arow[i] = min(m0 + sr[i], M - 1);
        brow[i] = n0 + sr[i];
    }

    auto stage_fill = [&](int buf, int k0) {
        float4 av[4], bv[4];
#pragma unroll
        for (int i = 0; i < 4; ++i) {
            av[i] = *(const float4*)(A + (size_t)arow[i] * K + k0 + kc4[i]);
            bv[i] = *(const float4*)(B + (size_t)brow[i] * K + k0 + kc4[i]);
        }
        uint32_t* Ad = As + buf * GM_STAGE;
        uint32_t* Bd = Bs + buf * GM_STAGE;
#pragma unroll
        for (int i = 0; i < 4; ++i) {
            uint32_t* pa = &Ad[sr[i] * GSTR + kc4[i]];
            pa[0] = f2tf(av[i].x); pa[1] = f2tf(av[i].y);
            pa[2] = f2tf(av[i].z); pa[3] = f2tf(av[i].w);
            uint32_t* pb = &Bd[sr[i] * GSTR + kc4[i]];
            pb[0] = f2tf(bv[i].x); pb[1] = f2tf(bv[i].y);
            pb[2] = f2tf(bv[i].z); pb[3] = f2tf(bv[i].w);
        }
    };

    stage_fill(0, 0);
    __syncthreads();

    float acc[16][4];
#pragma unroll
    for (int t = 0; t < 16; ++t)
        acc[t][0] = acc[t][1] = acc[t][2] = acc[t][3] = 0.f;

    const uint32_t As_u = smem_addr(As);
    const uint32_t Bs_u = smem_addr(Bs);

    int buf = 0;
    for (int k0 = 0; k0 < K; k0 += GM_BK) {
        // fill the free buffer for next iter (LDG latency covered by MMAs of other warps)
        if (k0 + GM_BK < K) stage_fill(buf ^ 1, k0 + GM_BK);

        const uint32_t Ab = As_u + 4u * (buf * GM_STAGE);
        const uint32_t Bb = Bs_u + 4u * (buf * GM_STAGE);
#pragma unroll
        for (int ks = 0; ks < 4; ++ks) {
            const int kb = ks * 8;
            uint32_t af[4][4], bf[4][2];
#pragma unroll
            for (int mt = 0; mt < 4; ++mt) {
                uint32_t addr = Ab + 4u * ((wm * 64 + mt * 16 + a_row) * GSTR + kb + a_ko);
                ldsm_x4(af[mt][0], af[mt][1], af[mt][2], af[mt][3], addr);
            }
#pragma unroll
            for (int p = 0; p < 2; ++p) {
                uint32_t addr = Bb + 4u * ((wn * 32 + p * 16 + b_row) * GSTR + kb + b_ko);
                ldsm_x4(bf[2*p][0], bf[2*p][1], bf[2*p+1][0], bf[2*p+1][1], addr);
            }
#pragma unroll
            for (int mt = 0; mt < 4; ++mt)
#pragma unroll
                for (int nt = 0; nt < 4; ++nt)
                    mma_tf32(acc[mt * 4 + nt],
                             af[mt][0], af[mt][1], af[mt][2], af[mt][3],
                             bf[nt][0], bf[nt][1]);
        }
        __syncthreads();
        buf ^= 1;
    }

    // epilogue
#pragma unroll
    for (int nt = 0; nt < 4; ++nt) {
        int c = n0 + wn * 32 + nt * 8 + (lane & 3) * 2;
        float b0 = bias[c], b1 = bias[c + 1];
#pragma unroll
        for (int mt = 0; mt < 4; ++mt) {
            int r = m0 + wm * 64 + mt * 16 + (lane >> 2);
            float* a4 = acc[mt * 4 + nt];
            if (r < M)
                *(float2*)(C + (size_t)r * N + c) = make_float2(a4[0] + b0, a4[1] + b1);
            if (r + 8 < M)
                *(float2*)(C + (size_t)(r + 8) * N + c) = make_float2(a4[2] + b0, a4[3] + b1);
        }
    }
}

__global__ void __launch_bounds__(256, 2) qkv_gemm_tf32(
    const float* __restrict__ x,
    const float* __restrict__ Wq, const float* __restrict__ bq,
    const float* __restrict__ Wk, const float* __restrict__ bk,
    const float* __restrict__ Wv, const float* __restrict__ bv)
{
    extern __shared__ __align__(16) uint32_t smw[];
    uint32_t* As = smw;                     // 2 stages
    uint32_t* Bs = smw + 2 * GM_STAGE;      // 2 stages
    const float* W; const float* b; float* out;
    if (blockIdx.z == 0)      { W = Wq; b = bq; out = g_q; }
    else if (blockIdx.z == 1) { W = Wk; b = bk; out = g_k; }
    else                      { W = Wv; b = bv; out = g_v; }
    gemm_tile_tf32(x, W, b, out, LTOK, DIM, DIM,
                   blockIdx.y * GM_BM, blockIdx.x * GM_BN, As, Bs);
}

__global__ void __launch_bounds__(256, 2) out_gemm_tf32(
    const float* __restrict__ Wo, const float* __restrict__ bo,
    float* __restrict__ out)
{
    extern __shared__ __align__(16) uint32_t smw[];
    uint32_t* As = smw;
    uint32_t* Bs = smw + 2 * GM_STAGE;
    gemm_tile_tf32(g_o, Wo, bo, out, LTOK, DIM, DIM,
                   blockIdx.y * GM_BM, blockIdx.x * GM_BN, As, Bs);
}

// ================= fused RMSNorm + RoPE (q and k) =================
__global__ void __launch_bounds__(256) rmsnorm_rope(
    const float* __restrict__ gq, const float* __restrict__ gk,
    const float* __restrict__ freqs, const int* __restrict__ gsz)
{
    const int t = blockIdx.x;
    const int which = blockIdx.y;
    float* row = (which ? g_k : g_q) + (size_t)t * DIM;
    const float* g = which ? gk : gq;
    const int tid = threadIdx.x;

    float ss = 0.f;
    for (int i = tid; i < DIM; i += 256) {
        float v = row[i];
        ss += v * v;
    }
    __shared__ float red[8];
#pragma unroll
    for (int o = 16; o; o >>= 1) ss += __shfl_xor_sync(0xffffffffu, ss, o);
    if ((tid & 31) == 0) red[tid >> 5] = ss;
    __syncthreads();
    if (tid < 8) {
        float v = red[tid];
#pragma unroll
        for (int o = 4; o; o >>= 1) v += __shfl_xor_sync(0xffu, v, o);
        if (tid == 0) red[0] = v;
    }
    __syncthreads();
    const float rms = rsqrtf(red[0] * (1.0f / DIM) + EPS);

    const int Hs = gsz[1], Ws = gsz[2];
    const int fi = t / (Hs * Ws);
    const int hi = (t / Ws) % Hs;
    const int wi = t % Ws;

    for (int p = tid; p < HEADS * 64; p += 256) {
        const int h = p >> 6;
        const int j = p & 63;
        const int pos = (j < 22) ? fi : ((j < 43) ? hi : wi);
        const float ang = freqs[pos * 64 + j];
        float c, s;
        sincosf(ang, &s, &c);
        const int d0 = h * HD + 2 * j;
        const float x0 = row[d0]     * rms * g[d0];
        const float x1 = row[d0 + 1] * rms * g[d0 + 1];
        row[d0]     = x0 * c - x1 * s;
        row[d0 + 1] = x0 * s + x1 * c;
    }
}

// ================= flash attention (tf32 mma + ldmatrix) =================
#define FQ 64
#define FK 64
#define QST 132     // 528B rows (33*16); %32=4 -> LDSM rows partition banks
#define KST 132
#define VST 136     // %32=8 -> conflict-free PV scalar B-frags
#define SST 68      // 272B rows (17*16); %32=4
#define FLASH_SMEM_FLOATS (FQ * QST + FK * VST + FQ * SST + 3 * FQ)

__global__ void __launch_bounds__(256, 2) flash_tf32()
{
    extern __shared__ float sm[];
    float* Qs  = sm;
    float* KVs = Qs + FQ * QST;
    float* Ss  = KVs + FK * VST;
    float* m_s = Ss + FQ * SST;
    float* l_s = m_s + FQ;
    float* f_s = l_s + FQ;
    uint32_t* Qu  = (uint32_t*)Qs;
    uint32_t* KVu = (uint32_t*)KVs;
    uint32_t* Su  = (uint32_t*)Ss;

    const int tid = threadIdx.x;
    const int lane = tid & 31;
    const int wid = tid >> 5;
    const int wm = wid >> 2;
    const int wn = wid & 3;
    const int h  = blockIdx.y;
    const int q0 = blockIdx.x * FQ;

    const int tr = lane & 7;
    const int mq = lane >> 3;
    const int a_row = tr + 8 * (mq & 1);
    const int a_ko  = 4 * (mq >> 1);
    const int b_row = tr + 8 * (mq >> 1);
    const int b_ko  = 4 * (mq & 1);

    const uint32_t Qa = smem_addr(Qu);
    const uint32_t Ka = smem_addr(KVu);
    const uint32_t Sa = smem_addr(Su);

    int srow[8], scol[8];
#pragma unroll
    for (int j = 0; j < 8; ++j) {
        int i = tid + j * 256;
        srow[j] = i >> 5;
        scol[j] = (i & 31) * 4;
    }

#pragma unroll
    for (int j = 0; j < 8; ++j) {
        float4 v = *(const float4*)(g_q + (size_t)(q0 + srow[j]) * DIM + h * HD + scol[j]);
        uint32_t* p = &Qu[srow[j] * QST + scol[j]];
        p[0] = f2tf(v.x * SCALE); p[1] = f2tf(v.y * SCALE);
        p[2] = f2tf(v.z * SCALE); p[3] = f2tf(v.w * SCALE);
    }
    if (tid < FQ) { m_s[tid] = -3.0e38f; l_s[tid] = 0.f; }

    float O[8][4];
#pragma unroll
    for (int t = 0; t < 8; ++t) O[t][0] = O[t][1] = O[t][2] = O[t][3] = 0.f;

    float4 kreg[8];
#pragma unroll
    for (int j = 0; j < 8; ++j)
        kreg[j] = *(const float4*)(g_k + (size_t)srow[j] * DIM + h * HD + scol[j]);

    for (int t0 = 0; t0 < LTOK; t0 += FK) {
        __syncthreads();   // (1) prev PV reads done
#pragma unroll
        for (int j = 0; j < 8; ++j) {
            uint32_t* p = &KVu[srow[j] * KST + scol[j]];
            p[0] = f2tf(kreg[j].x); p[1] = f2tf(kreg[j].y);
            p[2] = f2tf(kreg[j].z); p[3] = f2tf(kreg[j].w);
        }
        __syncthreads();   // (2) K visible

        float4 vreg[8];
#pragma unroll
        for (int j = 0; j < 8; ++j)
            vreg[j] = *(const float4*)(g_v + (size_t)(t0 + srow[j]) * DIM + h * HD + scol[j]);

        // S = Q K^T : warp tile 32(q) x 16(kv)
        float Sacc[2][2][4] = {};
#pragma unroll
        for (int ks = 0; ks < 16; ++ks) {
            const int kb = ks * 8;
            uint32_t af[2][4], bf[2][2];
#pragma unroll
            for (int mt = 0; mt < 2; ++mt) {
                uint32_t addr = Qa + 4u * ((wm * 32 + mt * 16 + a_row) * QST + kb + a_ko);
                ldsm_x4(af[mt][0], af[mt][1], af[mt][2], af[mt][3], addr);
            }
            {
                uint32_t addr = Ka + 4u * ((wn * 16 + b_row) * KST + kb + b_ko);
                ldsm_x4(bf[0][0], bf[0][1], bf[1][0], bf[1][1], addr);
            }
#pragma unroll
            for (int mt = 0; mt < 2; ++mt)
#pragma unroll
                for (int nt = 0; nt < 2; ++nt)
                    mma_tf32(Sacc[mt][nt],
                             af[mt][0], af[mt][1], af[mt][2], af[mt][3],
                             bf[nt][0], bf[nt][1]);
        }
#pragma unroll
        for (int mt = 0; mt < 2; ++mt) {
            int r = wm * 32 + mt * 16 + (lane >> 2);
#pragma unroll
            for (int nt = 0; nt < 2; ++nt) {
                int c = wn * 16 + nt * 8 + (lane & 3) * 2;
                *(float2*)&Ss[r * SST + c] = make_float2(Sacc[mt][nt][0], Sacc[mt][nt][1]);
                *(float2*)&Ss[(r + 8) * SST + c] = make_float2(Sacc[mt][nt][2], Sacc[mt][nt][3]);
            }
        }

        if (t0 + FK < LTOK) {
#pragma unroll
            for (int j = 0; j < 8; ++j)
                kreg[j] = *(const float4*)(g_k + (size_t)(t0 + FK + srow[j]) * DIM + h * HD + scol[j]);
        }
        __syncthreads();   // (3) Ss visible, KVs free

#pragma unroll
        for (int j = 0; j < 8; ++j) {
            uint32_t* p = &KVu[srow[j] * VST + scol[j]];
            p[0] = f2tf(vreg[j].x); p[1] = f2tf(vreg[j].y);
            p[2] = f2tf(vreg[j].z); p[3] = f2tf(vreg[j].w);
        }

        // online softmax (column-interleaved per seg)
        {
            const int row = tid >> 2;
            const int seg = tid & 3;
            const float mold = m_s[row];
            float vals[16];
            float tm = -3.0e38f;
#pragma unroll
            for (int c = 0; c < 16; ++c) {
                vals[c] = Ss[row * SST + seg + 4 * c];
                tm = fmaxf(tm, vals[c]);
            }
            tm = fmaxf(tm, __shfl_xor_sync(0xffffffffu, tm, 1));
            tm = fmaxf(tm, __shfl_xor_sync(0xffffffffu, tm, 2));
            const float mnew = fmaxf(mold, tm);
            float psum = 0.f;
#pragma unroll
            for (int c = 0; c < 16; ++c) {
                float p = __expf(vals[c] - mnew);
                psum += p;
                Su[row * SST + seg + 4 * c] = f2tf(p);
            }
            psum += __shfl_xor_sync(0xffffffffu, psum, 1);
            psum += __shfl_xor_sync(0xffffffffu, psum, 2);
            if (seg == 0) {
                float f = __expf(mold - mnew);
                f_s[row] = f;
                l_s[row] = l_s[row] * f + psum;
                m_s[row] = mnew;
            }
        }
        __syncthreads();   // (4) V + Su + f_s visible

        // O = O*f + P @ V : warp tile 32(q) x 32(hd)
#pragma unroll
        for (int mt = 0; mt < 2; ++mt) {
            int r = wm * 32 + mt * 16 + (lane >> 2);
            float f0 = f_s[r], f1 = f_s[r + 8];
#pragma unroll
            for (int nt = 0; nt < 4; ++nt) {
                O[mt * 4 + nt][0] *= f0; O[mt * 4 + nt][1] *= f0;
                O[mt * 4 + nt][2] *= f1; O[mt * 4 + nt][3] *= f1;
            }
        }
#pragma unroll
        for (int ks = 0; ks < 8; ++ks) {
            const int kb = ks * 8;
            uint32_t af[2][4], bf[4][2];
#pragma unroll
            for (int mt = 0; mt < 2; ++mt) {
                uint32_t addr = Sa + 4u * ((wm * 32 + mt * 16 + a_row) * SST + kb + a_ko);
                ldsm_x4(af[mt][0], af[mt][1], af[mt][2], af[mt][3], addr);
            }
#pragma unroll
            for (int nt = 0; nt < 4; ++nt) {
                int c = wn * 32 + nt * 8 + (lane >> 2);
                bf[nt][0] = KVu[(kb + (lane & 3)) * VST + c];
                bf[nt][1] = KVu[(kb + (lane & 3) + 4) * VST + c];
            }
#pragma unroll
            for (int mt = 0; mt < 2; ++mt)
#pragma unroll
                for (int nt = 0; nt < 4; ++nt)
                    mma_tf32(O[mt * 4 + nt],
                             af[mt][0], af[mt][1], af[mt][2], af[mt][3],
                             bf[nt][0], bf[nt][1]);
        }
    }

    // finalize
#pragma unroll
    for (int mt = 0; mt < 2; ++mt) {
        int r = wm * 32 + mt * 16 + (lane >> 2);
        float inv0 = 1.f / l_s[r], inv1 = 1.f / l_s[r + 8];
#pragma unroll
        for (int nt = 0; nt < 4; ++nt) {
            int c = wn * 32 + nt * 8 + (lane & 3) * 2;
            float* d0 = g_o + (size_t)(q0 + r) * DIM + h * HD + c;
            *(float2*)d0 = make_float2(O[mt * 4 + nt][0] * inv0, O[mt * 4 + nt][1] * inv0);
            float* d1 = g_o + (size_t)(q0 + r + 8) * DIM + h * HD + c;
            *(float2*)d1 = make_float2(O[mt * 4 + nt][2] * inv1, O[mt * 4 + nt][3] * inv1);
        }
    }
}

// ================= launch =================
extern "C" void kernel_launch(void* const* d_in, const int* in_sizes, int n_in,
                              void* d_out, int out_size)
{
    const float* x          = (const float*)d_in[0];
    const int*   grid_sizes = (const int*)d_in[2];
    const float* freqs      = (const float*)d_in[3];
    const float* Wq = (const float*)d_in[4];
    const float* bq = (const float*)d_in[5];
    const float* Wk = (const float*)d_in[6];
    const float* bk = (const float*)d_in[7];
    const float* Wv = (const float*)d_in[8];
    const float* bv = (const float*)d_in[9];
    const float* Wo = (const float*)d_in[10];
    const float* bo = (const float*)d_in[11];
    const float* gq = (const float*)d_in[12];
    const float* gk = (const float*)d_in[13];
    float* out = (float*)d_out;

    const int flash_smem = FLASH_SMEM_FLOATS * sizeof(float);
    cudaFuncSetAttribute(flash_tf32, cudaFuncAttributeMaxDynamicSharedMemorySize, flash_smem);
    cudaFuncSetAttribute(qkv_gemm_tf32, cudaFuncAttributeMaxDynamicSharedMemorySize, GM_SMEM_BYTES);
    cudaFuncSetAttribute(out_gemm_tf32, cudaFuncAttributeMaxDynamicSharedMemorySize, GM_SMEM_BYTES);

    dim3 gqkv(DIM / GM_BN, (LTOK + GM_BM - 1) / GM_BM, 3);   // 12 x 28 x 3
    dim3 gout(DIM / GM_BN, (LTOK + GM_BM - 1) / GM_BM);      // 12 x 28

    qkv_gemm_tf32<<<gqkv, 256, GM_SMEM_BYTES>>>(x, Wq, bq, Wk, bk, Wv, bv);
    rmsnorm_rope<<<dim3(LTOK, 2), 256>>>(gq, gk, freqs, grid_sizes);
    flash_tf32<<<dim3(LTOK / FQ, HEADS), 256, flash_smem>>>();
    out_gemm_tf32<<<gout, 256, GM_SMEM_BYTES>>>(Wo, bo, out);
}

// round 10
// speedup vs baseline: 1.0915x; 1.0915x over previous
#include <cuda_runtime.h>
#include <cstdint>

#define DIM    1536
#define HEADS  12
#define HD     128
#define LTOK   3520
#define EPS    1e-6f
#define SCALE  0.08838834764831845f   // 1/sqrt(128)

// ---------------- scratch (no allocation allowed) ----------------
__device__ float g_q[LTOK * DIM];
__device__ float g_k[LTOK * DIM];
__device__ float g_v[LTOK * DIM];
__device__ float g_o[LTOK * DIM];
__device__ uint32_t g_xt[LTOK * DIM];        // x pre-converted to tf32
__device__ uint32_t g_wt[4][DIM * DIM];      // Wq,Wk,Wv,Wo pre-converted
__device__ uint32_t g_ot[LTOK * DIM];        // attn out pre-converted

// ---------------- tf32 / ldmatrix / cp.async helpers ----------------
__device__ __forceinline__ uint32_t f2tf(float f) {
    uint32_t u;
    asm("cvt.rna.tf32.f32 %0, %1;" : "=r"(u) : "f"(f));
    return u;
}

__device__ __forceinline__ void mma_tf32(float c[4],
    uint32_t a0, uint32_t a1, uint32_t a2, uint32_t a3,
    uint32_t b0, uint32_t b1)
{
    asm volatile(
        "mma.sync.aligned.m16n8k8.row.col.f32.tf32.tf32.f32 "
        "{%0,%1,%2,%3}, {%4,%5,%6,%7}, {%8,%9}, {%0,%1,%2,%3};\n"
        : "+f"(c[0]), "+f"(c[1]), "+f"(c[2]), "+f"(c[3])
        : "r"(a0), "r"(a1), "r"(a2), "r"(a3), "r"(b0), "r"(b1));
}

__device__ __forceinline__ void ldsm_x4(uint32_t& r0, uint32_t& r1,
                                        uint32_t& r2, uint32_t& r3, uint32_t addr)
{
    asm volatile("ldmatrix.sync.aligned.m8n8.x4.shared.b16 {%0,%1,%2,%3}, [%4];"
                 : "=r"(r0), "=r"(r1), "=r"(r2), "=r"(r3) : "r"(addr));
}
__device__ __forceinline__ uint32_t smem_addr(const void* p) {
    return (uint32_t)__cvta_generic_to_shared(p);
}
__device__ __forceinline__ void cp_async16(uint32_t dst, const void* src) {
    asm volatile("cp.async.cg.shared.global [%0], [%1], 16;" :: "r"(dst), "l"(src));
}
#define CP_COMMIT() asm volatile("cp.async.commit_group;" ::: "memory")
#define CP_WAIT1()  asm volatile("cp.async.wait_group 1;" ::: "memory")

// ================= tf32 convert kernel (gmem -> gmem) =================
__global__ void __launch_bounds__(256) convert_tf32(const float4* __restrict__ src,
                                                    uint4* __restrict__ dst, int n4)
{
    int i = blockIdx.x * blockDim.x + threadIdx.x;
    if (i < n4) {
        float4 v = src[i];
        dst[i] = make_uint4(f2tf(v.x), f2tf(v.y), f2tf(v.z), f2tf(v.w));
    }
}

// ================= tf32 GEMM (pre-converted): C = A @ B^T + bias =========
// BM=BN=128, BK=32, 256 threads (8 warps 2x4), warp tile 64x32.
// 3-stage cp.async ring, one barrier + one commit_group per K-iter.
#define GM_BM 128
#define GM_BN 128
#define GM_BK 32
#define GSTR  36   // row stride words (144B); %32=4 -> conflict-free LDSM
#define GM_TILE_W (GM_BM * GSTR)          // words per operand tile (4608)
#define GM_STAGE_W (2 * GM_TILE_W)        // A + B
#define GM_SMEM_BYTES (3 * GM_STAGE_W * 4)  // 110592

__device__ __forceinline__ void gemm_tile_pre(
    const uint32_t* __restrict__ A, const uint32_t* __restrict__ B,
    const float* __restrict__ bias, float* __restrict__ C,
    int M, int N, int K, int m0, int n0, uint32_t* sm)
{
    const int tid = threadIdx.x;
    const int lane = tid & 31;
    const int wid = tid >> 5;
    const int wm = wid >> 2;
    const int wn = wid & 3;

    const int tr = lane & 7;
    const int mq = lane >> 3;
    const int a_row = tr + 8 * (mq & 1);
    const int a_ko  = 4 * (mq >> 1);
    const int b_row = tr + 8 * (mq >> 1);
    const int b_ko  = 4 * (mq & 1);

    const int kc = (tid & 7) * 4;     // word offset within BK=32 row
    int sr[4], arow[4], brow[4];
#pragma unroll
    for (int i = 0; i < 4; ++i) {
        int s = tid + i * 256;
        sr[i]  = s >> 3;              // 0..127
        arow[i] = min(m0 + sr[i], M - 1);
        brow[i] = n0 + sr[i];
    }

    const uint32_t smu = smem_addr(sm);

    auto fill = [&](int st, int k0) {
        const uint32_t base = smu + 4u * (st * GM_STAGE_W);
#pragma unroll
        for (int i = 0; i < 4; ++i)
            cp_async16(base + 4u * (sr[i] * GSTR + kc),
                       A + (size_t)arow[i] * K + k0 + kc);
#pragma unroll
        for (int i = 0; i < 4; ++i)
            cp_async16(base + 4u * (GM_TILE_W + sr[i] * GSTR + kc),
                       B + (size_t)brow[i] * K + k0 + kc);
        CP_COMMIT();
    };

    fill(0, 0);
    fill(1, GM_BK);

    float acc[16][4];
#pragma unroll
    for (int t = 0; t < 16; ++t)
        acc[t][0] = acc[t][1] = acc[t][2] = acc[t][3] = 0.f;

    const int NIT = K / GM_BK;   // 48
    int st = 0;
    for (int it = 0; it < NIT; ++it) {
        CP_WAIT1();              // stage `it` landed (≤1 group outstanding)
        __syncthreads();         // visible to all; prev compute done -> next buf free
        if (it + 2 < NIT) fill((st + 2) % 3, (it + 2) * GM_BK);
        else CP_COMMIT();        // keep group count uniform

        const uint32_t Ab = smu + 4u * (st * GM_STAGE_W);
        const uint32_t Bb = Ab + 4u * GM_TILE_W;
#pragma unroll
        for (int ks = 0; ks < 4; ++ks) {
            const int kb = ks * 8;
            uint32_t af[4][4], bf[4][2];
#pragma unroll
            for (int mt = 0; mt < 4; ++mt) {
                uint32_t addr = Ab + 4u * ((wm * 64 + mt * 16 + a_row) * GSTR + kb + a_ko);
                ldsm_x4(af[mt][0], af[mt][1], af[mt][2], af[mt][3], addr);
            }
#pragma unroll
            for (int p = 0; p < 2; ++p) {
                uint32_t addr = Bb + 4u * ((wn * 32 + p * 16 + b_row) * GSTR + kb + b_ko);
                ldsm_x4(bf[2*p][0], bf[2*p][1], bf[2*p+1][0], bf[2*p+1][1], addr);
            }
#pragma unroll
            for (int mt = 0; mt < 4; ++mt)
#pragma unroll
                for (int nt = 0; nt < 4; ++nt)
                    mma_tf32(acc[mt * 4 + nt],
                             af[mt][0], af[mt][1], af[mt][2], af[mt][3],
                             bf[nt][0], bf[nt][1]);
        }
        st = (st + 1) % 3;
    }

    // epilogue
#pragma unroll
    for (int nt = 0; nt < 4; ++nt) {
        int c = n0 + wn * 32 + nt * 8 + (lane & 3) * 2;
        float b0 = bias[c], b1 = bias[c + 1];
#pragma unroll
        for (int mt = 0; mt < 4; ++mt) {
            int r = m0 + wm * 64 + mt * 16 + (lane >> 2);
            float* a4 = acc[mt * 4 + nt];
            if (r < M)
                *(float2*)(C + (size_t)r * N + c) = make_float2(a4[0] + b0, a4[1] + b1);
            if (r + 8 < M)
                *(float2*)(C + (size_t)(r + 8) * N + c) = make_float2(a4[2] + b0, a4[3] + b1);
        }
    }
}

__global__ void __launch_bounds__(256, 2) qkv_gemm_tf32(
    const float* __restrict__ bq, const float* __restrict__ bk,
    const float* __restrict__ bv)
{
    extern __shared__ __align__(16) uint32_t smw[];
    const float* b; float* out;
    if (blockIdx.z == 0)      { b = bq; out = g_q; }
    else if (blockIdx.z == 1) { b = bk; out = g_k; }
    else                      { b = bv; out = g_v; }
    gemm_tile_pre(g_xt, g_wt[blockIdx.z], b, out, LTOK, DIM, DIM,
                  blockIdx.y * GM_BM, blockIdx.x * GM_BN, smw);
}

__global__ void __launch_bounds__(256, 2) out_gemm_tf32(
    const float* __restrict__ bo, float* __restrict__ out)
{
    extern __shared__ __align__(16) uint32_t smw[];
    gemm_tile_pre(g_ot, g_wt[3], bo, out, LTOK, DIM, DIM,
                  blockIdx.y * GM_BM, blockIdx.x * GM_BN, smw);
}

// ================= fused RMSNorm + RoPE (q and k) =================
__global__ void __launch_bounds__(256) rmsnorm_rope(
    const float* __restrict__ gq, const float* __restrict__ gk,
    const float* __restrict__ freqs, const int* __restrict__ gsz)
{
    const int t = blockIdx.x;
    const int which = blockIdx.y;
    float* row = (which ? g_k : g_q) + (size_t)t * DIM;
    const float* g = which ? gk : gq;
    const int tid = threadIdx.x;

    float ss = 0.f;
    for (int i = tid; i < DIM; i += 256) {
        float v = row[i];
        ss += v * v;
    }
    __shared__ float red[8];
#pragma unroll
    for (int o = 16; o; o >>= 1) ss += __shfl_xor_sync(0xffffffffu, ss, o);
    if ((tid & 31) == 0) red[tid >> 5] = ss;
    __syncthreads();
    if (tid < 8) {
        float v = red[tid];
#pragma unroll
        for (int o = 4; o; o >>= 1) v += __shfl_xor_sync(0xffu, v, o);
        if (tid == 0) red[0] = v;
    }
    __syncthreads();
    const float rms = rsqrtf(red[0] * (1.0f / DIM) + EPS);

    const int Hs = gsz[1], Ws = gsz[2];
    const int fi = t / (Hs * Ws);
    const int hi = (t / Ws) % Hs;
    const int wi = t % Ws;

    for (int p = tid; p < HEADS * 64; p += 256) {
        const int h = p >> 6;
        const int j = p & 63;
        const int pos = (j < 22) ? fi : ((j < 43) ? hi : wi);
        const float ang = freqs[pos * 64 + j];
        float c, s;
        sincosf(ang, &s, &c);
        const int d0 = h * HD + 2 * j;
        const float x0 = row[d0]     * rms * g[d0];
        const float x1 = row[d0 + 1] * rms * g[d0 + 1];
        row[d0]     = x0 * c - x1 * s;
        row[d0 + 1] = x0 * s + x1 * c;
    }
}

// ================= flash attention (tf32 mma + ldmatrix) =================
#define FQ 64
#define FK 64
#define QST 132
#define KST 132
#define VST 136
#define SST 68
#define FLASH_SMEM_FLOATS (FQ * QST + FK * VST + FQ * SST + 3 * FQ)

__global__ void __launch_bounds__(256, 2) flash_tf32()
{
    extern __shared__ float sm[];
    float* Qs  = sm;
    float* KVs = Qs + FQ * QST;
    float* Ss  = KVs + FK * VST;
    float* m_s = Ss + FQ * SST;
    float* l_s = m_s + FQ;
    float* f_s = l_s + FQ;
    uint32_t* Qu  = (uint32_t*)Qs;
    uint32_t* KVu = (uint32_t*)KVs;
    uint32_t* Su  = (uint32_t*)Ss;

    const int tid = threadIdx.x;
    const int lane = tid & 31;
    const int wid = tid >> 5;
    const int wm = wid >> 2;
    const int wn = wid & 3;
    const int h  = blockIdx.y;
    const int q0 = blockIdx.x * FQ;

    const int tr = lane & 7;
    const int mq = lane >> 3;
    const int a_row = tr + 8 * (mq & 1);
    const int a_ko  = 4 * (mq >> 1);
    const int b_row = tr + 8 * (mq >> 1);
    const int b_ko  = 4 * (mq & 1);

    const uint32_t Qa = smem_addr(Qu);
    const uint32_t Ka = smem_addr(KVu);
    const uint32_t Sa = smem_addr(Su);

    int srow[8], scol[8];
#pragma unroll
    for (int j = 0; j < 8; ++j) {
        int i = tid + j * 256;
        srow[j] = i >> 5;
        scol[j] = (i & 31) * 4;
    }

#pragma unroll
    for (int j = 0; j < 8; ++j) {
        float4 v = *(const float4*)(g_q + (size_t)(q0 + srow[j]) * DIM + h * HD + scol[j]);
        uint32_t* p = &Qu[srow[j] * QST + scol[j]];
        p[0] = f2tf(v.x * SCALE); p[1] = f2tf(v.y * SCALE);
        p[2] = f2tf(v.z * SCALE); p[3] = f2tf(v.w * SCALE);
    }
    if (tid < FQ) { m_s[tid] = -3.0e38f; l_s[tid] = 0.f; }

    float O[8][4];
#pragma unroll
    for (int t = 0; t < 8; ++t) O[t][0] = O[t][1] = O[t][2] = O[t][3] = 0.f;

    float4 kreg[8];
#pragma unroll
    for (int j = 0; j < 8; ++j)
        kreg[j] = *(const float4*)(g_k + (size_t)srow[j] * DIM + h * HD + scol[j]);

    for (int t0 = 0; t0 < LTOK; t0 += FK) {
        __syncthreads();   // (1) prev PV reads done
#pragma unroll
        for (int j = 0; j < 8; ++j) {
            uint32_t* p = &KVu[srow[j] * KST + scol[j]];
            p[0] = f2tf(kreg[j].x); p[1] = f2tf(kreg[j].y);
            p[2] = f2tf(kreg[j].z); p[3] = f2tf(kreg[j].w);
        }
        __syncthreads();   // (2) K visible

        float4 vreg[8];
#pragma unroll
        for (int j = 0; j < 8; ++j)
            vreg[j] = *(const float4*)(g_v + (size_t)(t0 + srow[j]) * DIM + h * HD + scol[j]);

        float Sacc[2][2][4] = {};
#pragma unroll
        for (int ks = 0; ks < 16; ++ks) {
            const int kb = ks * 8;
            uint32_t af[2][4], bf[2][2];
#pragma unroll
            for (int mt = 0; mt < 2; ++mt) {
                uint32_t addr = Qa + 4u * ((wm * 32 + mt * 16 + a_row) * QST + kb + a_ko);
                ldsm_x4(af[mt][0], af[mt][1], af[mt][2], af[mt][3], addr);
            }
            {
                uint32_t addr = Ka + 4u * ((wn * 16 + b_row) * KST + kb + b_ko);
                ldsm_x4(bf[0][0], bf[0][1], bf[1][0], bf[1][1], addr);
            }
#pragma unroll
            for (int mt = 0; mt < 2; ++mt)
#pragma unroll
                for (int nt = 0; nt < 2; ++nt)
                    mma_tf32(Sacc[mt][nt],
                             af[mt][0], af[mt][1], af[mt][2], af[mt][3],
                             bf[nt][0], bf[nt][1]);
        }
#pragma unroll
        for (int mt = 0; mt < 2; ++mt) {
            int r = wm * 32 + mt * 16 + (lane >> 2);
#pragma unroll
            for (int nt = 0; nt < 2; ++nt) {
                int c = wn * 16 + nt * 8 + (lane & 3) * 2;
                *(float2*)&Ss[r * SST + c] = make_float2(Sacc[mt][nt][0], Sacc[mt][nt][1]);
                *(float2*)&Ss[(r + 8) * SST + c] = make_float2(Sacc[mt][nt][2], Sacc[mt][nt][3]);
            }
        }

        if (t0 + FK < LTOK) {
#pragma unroll
            for (int j = 0; j < 8; ++j)
                kreg[j] = *(const float4*)(g_k + (size_t)(t0 + FK + srow[j]) * DIM + h * HD + scol[j]);
        }
        __syncthreads();   // (3) Ss visible, KVs free

#pragma unroll
        for (int j = 0; j < 8; ++j) {
            uint32_t* p = &KVu[srow[j] * VST + scol[j]];
            p[0] = f2tf(vreg[j].x); p[1] = f2tf(vreg[j].y);
            p[2] = f2tf(vreg[j].z); p[3] = f2tf(vreg[j].w);
        }

        {
            const int row = tid >> 2;
            const int seg = tid & 3;
            const float mold = m_s[row];
            float vals[16];
            float tm = -3.0e38f;
#pragma unroll
            for (int c = 0; c < 16; ++c) {
                vals[c] = Ss[row * SST + seg + 4 * c];
                tm = fmaxf(tm, vals[c]);
            }
            tm = fmaxf(tm, __shfl_xor_sync(0xffffffffu, tm, 1));
            tm = fmaxf(tm, __shfl_xor_sync(0xffffffffu, tm, 2));
            const float mnew = fmaxf(mold, tm);
            float psum = 0.f;
#pragma unroll
            for (int c = 0; c < 16; ++c) {
                float p = __expf(vals[c] - mnew);
                psum += p;
                Su[row * SST + seg + 4 * c] = f2tf(p);
            }
            psum += __shfl_xor_sync(0xffffffffu, psum, 1);
            psum += __shfl_xor_sync(0xffffffffu, psum, 2);
            if (seg == 0) {
                float f = __expf(mold - mnew);
                f_s[row] = f;
                l_s[row] = l_s[row] * f + psum;
                m_s[row] = mnew;
            }
        }
        __syncthreads();   // (4) V + Su + f_s visible

#pragma unroll
        for (int mt = 0; mt < 2; ++mt) {
            int r = wm * 32 + mt * 16 + (lane >> 2);
            float f0 = f_s[r], f1 = f_s[r + 8];
#pragma unroll
            for (int nt = 0; nt < 4; ++nt) {
                O[mt * 4 + nt][0] *= f0; O[mt * 4 + nt][1] *= f0;
                O[mt * 4 + nt][2] *= f1; O[mt * 4 + nt][3] *= f1;
            }
        }
#pragma unroll
        for (int ks = 0; ks < 8; ++ks) {
            const int kb = ks * 8;
            uint32_t af[2][4], bf[4][2];
#pragma unroll
            for (int mt = 0; mt < 2; ++mt) {
                uint32_t addr = Sa + 4u * ((wm * 32 + mt * 16 + a_row) * SST + kb + a_ko);
                ldsm_x4(af[mt][0], af[mt][1], af[mt][2], af[mt][3], addr);
            }
#pragma unroll
            for (int nt = 0; nt < 4; ++nt) {
                int c = wn * 32 + nt * 8 + (lane >> 2);
                bf[nt][0] = KVu[(kb + (lane & 3)) * VST + c];
                bf[nt][1] = KVu[(kb + (lane & 3) + 4) * VST + c];
            }
#pragma unroll
            for (int mt = 0; mt < 2; ++mt)
#pragma unroll
                for (int nt = 0; nt < 4; ++nt)
                    mma_tf32(O[mt * 4 + nt],
                             af[mt][0], af[mt][1], af[mt][2], af[mt][3],
                             bf[nt][0], bf[nt][1]);
        }
    }

    // finalize
#pragma unroll
    for (int mt = 0; mt < 2; ++mt) {
        int r = wm * 32 + mt * 16 + (lane >> 2);
        float inv0 = 1.f / l_s[r], inv1 = 1.f / l_s[r + 8];
#pragma unroll
        for (int nt = 0; nt < 4; ++nt) {
            int c = wn * 32 + nt * 8 + (lane & 3) * 2;
            float* d0 = g_o + (size_t)(q0 + r) * DIM + h * HD + c;
            *(float2*)d0 = make_float2(O[mt * 4 + nt][0] * inv0, O[mt * 4 + nt][1] * inv0);
            float* d1 = g_o + (size_t)(q0 + r + 8) * DIM + h * HD + c;
            *(float2*)d1 = make_float2(O[mt * 4 + nt][2] * inv1, O[mt * 4 + nt][3] * inv1);
        }
    }
}

// ================= launch =================
extern "C" void kernel_launch(void* const* d_in, const int* in_sizes, int n_in,
                              void* d_out, int out_size)
{
    const float* x          = (const float*)d_in[0];
    const int*   grid_sizes = (const int*)d_in[2];
    const float* freqs      = (const float*)d_in[3];
    const float* Wq = (const float*)d_in[4];
    const float* bq = (const float*)d_in[5];
    const float* Wk = (const float*)d_in[6];
    const float* bk = (const float*)d_in[7];
    const float* Wv = (const float*)d_in[8];
    const float* bv = (const float*)d_in[9];
    const float* Wo = (const float*)d_in[10];
    const float* bo = (const float*)d_in[11];
    const float* gq = (const float*)d_in[12];
    const float* gk = (const float*)d_in[13];
    float* out = (float*)d_out;

    uint32_t *xt, *wt, *ot;
    float* op;
    cudaGetSymbolAddress((void**)&xt, g_xt);
    cudaGetSymbolAddress((void**)&wt, g_wt);
    cudaGetSymbolAddress((void**)&ot, g_ot);
    cudaGetSymbolAddress((void**)&op, g_o);

    const int flash_smem = FLASH_SMEM_FLOATS * sizeof(float);
    cudaFuncSetAttribute(flash_tf32, cudaFuncAttributeMaxDynamicSharedMemorySize, flash_smem);
    cudaFuncSetAttribute(qkv_gemm_tf32, cudaFuncAttributeMaxDynamicSharedMemorySize, GM_SMEM_BYTES);
    cudaFuncSetAttribute(out_gemm_tf32, cudaFuncAttributeMaxDynamicSharedMemorySize, GM_SMEM_BYTES);

    const int NX4 = LTOK * DIM / 4;    // x / o element count in float4
    const int NW4 = DIM * DIM / 4;

    // pre-convert x and weights to tf32
    convert_tf32<<<(NX4 + 255) / 256, 256>>>((const float4*)x,  (uint4*)xt, NX4);
    convert_tf32<<<(NW4 + 255) / 256, 256>>>((const float4*)Wq, (uint4*)(wt + 0 * (size_t)DIM * DIM), NW4);
    convert_tf32<<<(NW4 + 255) / 256, 256>>>((const float4*)Wk, (uint4*)(wt + 1 * (size_t)DIM * DIM), NW4);
    convert_tf32<<<(NW4 + 255) / 256, 256>>>((const float4*)Wv, (uint4*)(wt + 2 * (size_t)DIM * DIM), NW4);
    convert_tf32<<<(NW4 + 255) / 256, 256>>>((const float4*)Wo, (uint4*)(wt + 3 * (size_t)DIM * DIM), NW4);

    dim3 gqkv(DIM / GM_BN, (LTOK + GM_BM - 1) / GM_BM, 3);   // 12 x 28 x 3
    dim3 gout(DIM / GM_BN, (LTOK + GM_BM - 1) / GM_BM);      // 12 x 28

    qkv_gemm_tf32<<<gqkv, 256, GM_SMEM_BYTES>>>(bq, bk, bv);
    rmsnorm_rope<<<dim3(LTOK, 2), 256>>>(gq, gk, freqs, grid_sizes);
    flash_tf32<<<dim3(LTOK / FQ, HEADS), 256, flash_smem>>>();
    convert_tf32<<<(NX4 + 255) / 256, 256>>>((const float4*)op, (uint4*)ot, NX4);
    out_gemm_tf32<<<gout, 256, GM_SMEM_BYTES>>>(bo, out);
}

// round 11
// speedup vs baseline: 1.1002x; 1.0080x over previous
#include <cuda_runtime.h>
#include <cstdint>

#define DIM    1536
#define HEADS  12
#define HD     128
#define LTOK   3520
#define EPS    1e-6f
#define SCALE  0.08838834764831845f   // 1/sqrt(128)

// ---------------- scratch (no allocation allowed) ----------------
__device__ float g_q[LTOK * DIM];
__device__ float g_k[LTOK * DIM];
__device__ float g_v[LTOK * DIM];
__device__ float g_o[LTOK * DIM];
__device__ uint32_t g_xt[LTOK * DIM];        // x pre-converted to tf32
__device__ uint32_t g_wt[4][DIM * DIM];      // Wq,Wk,Wv,Wo pre-converted
__device__ uint32_t g_ot[LTOK * DIM];        // attn out pre-converted
__device__ uint32_t g_qt[LTOK * DIM];        // rmsnorm+rope q, *SCALE, tf32
__device__ uint32_t g_kt[LTOK * DIM];        // rmsnorm+rope k, tf32
__device__ uint32_t g_vt[LTOK * DIM];        // v, tf32

// ---------------- tf32 / ldmatrix / cp.async helpers ----------------
__device__ __forceinline__ uint32_t f2tf(float f) {
    uint32_t u;
    asm("cvt.rna.tf32.f32 %0, %1;" : "=r"(u) : "f"(f));
    return u;
}

__device__ __forceinline__ void mma_tf32(float c[4],
    uint32_t a0, uint32_t a1, uint32_t a2, uint32_t a3,
    uint32_t b0, uint32_t b1)
{
    asm volatile(
        "mma.sync.aligned.m16n8k8.row.col.f32.tf32.tf32.f32 "
        "{%0,%1,%2,%3}, {%4,%5,%6,%7}, {%8,%9}, {%0,%1,%2,%3};\n"
        : "+f"(c[0]), "+f"(c[1]), "+f"(c[2]), "+f"(c[3])
        : "r"(a0), "r"(a1), "r"(a2), "r"(a3), "r"(b0), "r"(b1));
}

__device__ __forceinline__ void ldsm_x4(uint32_t& r0, uint32_t& r1,
                                        uint32_t& r2, uint32_t& r3, uint32_t addr)
{
    asm volatile("ldmatrix.sync.aligned.m8n8.x4.shared.b16 {%0,%1,%2,%3}, [%4];"
                 : "=r"(r0), "=r"(r1), "=r"(r2), "=r"(r3) : "r"(addr));
}
__device__ __forceinline__ uint32_t smem_addr(const void* p) {
    return (uint32_t)__cvta_generic_to_shared(p);
}
__device__ __forceinline__ void cp_async16(uint32_t dst, const void* src) {
    asm volatile("cp.async.cg.shared.global [%0], [%1], 16;" :: "r"(dst), "l"(src));
}
#define CP_COMMIT() asm volatile("cp.async.commit_group;" ::: "memory")
#define CP_WAIT1()  asm volatile("cp.async.wait_group 1;" ::: "memory")

// ================= tf32 convert kernel (gmem -> gmem) =================
__global__ void __launch_bounds__(256) convert_tf32(const float4* __restrict__ src,
                                                    uint4* __restrict__ dst, int n4)
{
    int i = blockIdx.x * blockDim.x + threadIdx.x;
    if (i < n4) {
        float4 v = src[i];
        dst[i] = make_uint4(f2tf(v.x), f2tf(v.y), f2tf(v.z), f2tf(v.w));
    }
}

// ================= tf32 GEMM (pre-converted): C = A @ B^T + bias =========
#define GM_BM 128
#define GM_BN 128
#define GM_BK 32
#define GSTR  36   // row stride words (144B); %32=4 -> conflict-free LDSM
#define GM_TILE_W (GM_BM * GSTR)
#define GM_STAGE_W (2 * GM_TILE_W)
#define GM_SMEM_BYTES (3 * GM_STAGE_W * 4)

__device__ __forceinline__ void gemm_tile_pre(
    const uint32_t* __restrict__ A, const uint32_t* __restrict__ B,
    const float* __restrict__ bias, float* __restrict__ C,
    int M, int N, int K, int m0, int n0, uint32_t* sm)
{
    const int tid = threadIdx.x;
    const int lane = tid & 31;
    const int wid = tid >> 5;
    const int wm = wid >> 2;
    const int wn = wid & 3;

    const int tr = lane & 7;
    const int mq = lane >> 3;
    const int a_row = tr + 8 * (mq & 1);
    const int a_ko  = 4 * (mq >> 1);
    const int b_row = tr + 8 * (mq >> 1);
    const int b_ko  = 4 * (mq & 1);

    const int kc = (tid & 7) * 4;
    int sr[4], arow[4], brow[4];
#pragma unroll
    for (int i = 0; i < 4; ++i) {
        int s = tid + i * 256;
        sr[i]  = s >> 3;
        arow[i] = min(m0 + sr[i], M - 1);
        brow[i] = n0 + sr[i];
    }

    const uint32_t smu = smem_addr(sm);

    auto fill = [&](int st, int k0) {
        const uint32_t base = smu + 4u * (st * GM_STAGE_W);
#pragma unroll
        for (int i = 0; i < 4; ++i)
            cp_async16(base + 4u * (sr[i] * GSTR + kc),
                       A + (size_t)arow[i] * K + k0 + kc);
#pragma unroll
        for (int i = 0; i < 4; ++i)
            cp_async16(base + 4u * (GM_TILE_W + sr[i] * GSTR + kc),
                       B + (size_t)brow[i] * K + k0 + kc);
        CP_COMMIT();
    };

    fill(0, 0);
    fill(1, GM_BK);

    float acc[16][4];
#pragma unroll
    for (int t = 0; t < 16; ++t)
        acc[t][0] = acc[t][1] = acc[t][2] = acc[t][3] = 0.f;

    const int NIT = K / GM_BK;
    int st = 0;
    for (int it = 0; it < NIT; ++it) {
        CP_WAIT1();
        __syncthreads();
        if (it + 2 < NIT) fill((st + 2) % 3, (it + 2) * GM_BK);
        else CP_COMMIT();

        const uint32_t Ab = smu + 4u * (st * GM_STAGE_W);
        const uint32_t Bb = Ab + 4u * GM_TILE_W;
#pragma unroll
        for (int ks = 0; ks < 4; ++ks) {
            const int kb = ks * 8;
            uint32_t af[4][4], bf[4][2];
#pragma unroll
            for (int mt = 0; mt < 4; ++mt) {
                uint32_t addr = Ab + 4u * ((wm * 64 + mt * 16 + a_row) * GSTR + kb + a_ko);
                ldsm_x4(af[mt][0], af[mt][1], af[mt][2], af[mt][3], addr);
            }
#pragma unroll
            for (int p = 0; p < 2; ++p) {
                uint32_t addr = Bb + 4u * ((wn * 32 + p * 16 + b_row) * GSTR + kb + b_ko);
                ldsm_x4(bf[2*p][0], bf[2*p][1], bf[2*p+1][0], bf[2*p+1][1], addr);
            }
#pragma unroll
            for (int mt = 0; mt < 4; ++mt)
#pragma unroll
                for (int nt = 0; nt < 4; ++nt)
                    mma_tf32(acc[mt * 4 + nt],
                             af[mt][0], af[mt][1], af[mt][2], af[mt][3],
                             bf[nt][0], bf[nt][1]);
        }
        st = (st + 1) % 3;
    }

    // epilogue
#pragma unroll
    for (int nt = 0; nt < 4; ++nt) {
        int c = n0 + wn * 32 + nt * 8 + (lane & 3) * 2;
        float b0 = bias[c], b1 = bias[c + 1];
#pragma unroll
        for (int mt = 0; mt < 4; ++mt) {
            int r = m0 + wm * 64 + mt * 16 + (lane >> 2);
            float* a4 = acc[mt * 4 + nt];
            if (r < M)
                *(float2*)(C + (size_t)r * N + c) = make_float2(a4[0] + b0, a4[1] + b1);
            if (r + 8 < M)
                *(float2*)(C + (size_t)(r + 8) * N + c) = make_float2(a4[2] + b0, a4[3] + b1);
        }
    }
}

__global__ void __launch_bounds__(256, 2) qkv_gemm_tf32(
    const float* __restrict__ bq, const float* __restrict__ bk,
    const float* __restrict__ bv)
{
    extern __shared__ __align__(16) uint32_t smw[];
    const float* b; float* out;
    if (blockIdx.z == 0)      { b = bq; out = g_q; }
    else if (blockIdx.z == 1) { b = bk; out = g_k; }
    else                      { b = bv; out = g_v; }
    gemm_tile_pre(g_xt, g_wt[blockIdx.z], b, out, LTOK, DIM, DIM,
                  blockIdx.y * GM_BM, blockIdx.x * GM_BN, smw);
}

__global__ void __launch_bounds__(256, 2) out_gemm_tf32(
    const float* __restrict__ bo, float* __restrict__ out)
{
    extern __shared__ __align__(16) uint32_t smw[];
    gemm_tile_pre(g_ot, g_wt[3], bo, out, LTOK, DIM, DIM,
                  blockIdx.y * GM_BM, blockIdx.x * GM_BN, smw);
}

// ============ fused RMSNorm + RoPE -> tf32 outputs (q scaled) ============
__global__ void __launch_bounds__(256) rmsnorm_rope(
    const float* __restrict__ gq, const float* __restrict__ gk,
    const float* __restrict__ freqs, const int* __restrict__ gsz)
{
    const int t = blockIdx.x;
    const int which = blockIdx.y;
    const float* row = (which ? g_k : g_q) + (size_t)t * DIM;
    uint32_t* rowo = (which ? g_kt : g_qt) + (size_t)t * DIM;
    const float oscale = which ? 1.0f : SCALE;
    const float* g = which ? gk : gq;
    const int tid = threadIdx.x;

    float ss = 0.f;
    for (int i = tid; i < DIM; i += 256) {
        float v = row[i];
        ss += v * v;
    }
    __shared__ float red[8];
#pragma unroll
    for (int o = 16; o; o >>= 1) ss += __shfl_xor_sync(0xffffffffu, ss, o);
    if ((tid & 31) == 0) red[tid >> 5] = ss;
    __syncthreads();
    if (tid < 8) {
        float v = red[tid];
#pragma unroll
        for (int o = 4; o; o >>= 1) v += __shfl_xor_sync(0xffu, v, o);
        if (tid == 0) red[0] = v;
    }
    __syncthreads();
    const float rms = rsqrtf(red[0] * (1.0f / DIM) + EPS);

    const int Hs = gsz[1], Ws = gsz[2];
    const int fi = t / (Hs * Ws);
    const int hi = (t / Ws) % Hs;
    const int wi = t % Ws;

    for (int p = tid; p < HEADS * 64; p += 256) {
        const int h = p >> 6;
        const int j = p & 63;
        const int pos = (j < 22) ? fi : ((j < 43) ? hi : wi);
        const float ang = freqs[pos * 64 + j];
        float c, s;
        sincosf(ang, &s, &c);
        const int d0 = h * HD + 2 * j;
        const float x0 = row[d0]     * rms * g[d0];
        const float x1 = row[d0 + 1] * rms * g[d0 + 1];
        rowo[d0]     = f2tf((x0 * c - x1 * s) * oscale);
        rowo[d0 + 1] = f2tf((x0 * s + x1 * c) * oscale);
    }
}

// ====== flash attention (tf32 mma + ldmatrix, pre-converted q/k/v) ======
#define FQ 64
#define FK 64
#define QST 132
#define KST 132
#define VST 136
#define SST 68
#define FLASH_SMEM_FLOATS (FQ * QST + FK * VST + FQ * SST + 3 * FQ)

__global__ void __launch_bounds__(256, 2) flash_tf32()
{
    extern __shared__ float sm[];
    float* Qs  = sm;
    float* KVs = Qs + FQ * QST;
    float* Ss  = KVs + FK * VST;
    float* m_s = Ss + FQ * SST;
    float* l_s = m_s + FQ;
    float* f_s = l_s + FQ;
    uint32_t* Qu  = (uint32_t*)Qs;
    uint32_t* KVu = (uint32_t*)KVs;
    uint32_t* Su  = (uint32_t*)Ss;

    const int tid = threadIdx.x;
    const int lane = tid & 31;
    const int wid = tid >> 5;
    const int wm = wid >> 2;
    const int wn = wid & 3;
    const int h  = blockIdx.y;
    const int q0 = blockIdx.x * FQ;

    const int tr = lane & 7;
    const int mq = lane >> 3;
    const int a_row = tr + 8 * (mq & 1);
    const int a_ko  = 4 * (mq >> 1);
    const int b_row = tr + 8 * (mq >> 1);
    const int b_ko  = 4 * (mq & 1);

    const uint32_t Qa = smem_addr(Qu);
    const uint32_t Ka = smem_addr(KVu);
    const uint32_t Sa = smem_addr(Su);

    int srow[8], scol[8];
#pragma unroll
    for (int j = 0; j < 8; ++j) {
        int i = tid + j * 256;
        srow[j] = i >> 5;
        scol[j] = (i & 31) * 4;
    }

    // Q tile: already scaled + tf32 in gmem
#pragma unroll
    for (int j = 0; j < 8; ++j) {
        uint4 v = *(const uint4*)(g_qt + (size_t)(q0 + srow[j]) * DIM + h * HD + scol[j]);
        *(uint4*)&Qu[srow[j] * QST + scol[j]] = v;
    }
    if (tid < FQ) { m_s[tid] = -3.0e38f; l_s[tid] = 0.f; }

    float O[8][4];
#pragma unroll
    for (int t = 0; t < 8; ++t) O[t][0] = O[t][1] = O[t][2] = O[t][3] = 0.f;

    uint4 kreg[8];
#pragma unroll
    for (int j = 0; j < 8; ++j)
        kreg[j] = *(const uint4*)(g_kt + (size_t)srow[j] * DIM + h * HD + scol[j]);

    for (int t0 = 0; t0 < LTOK; t0 += FK) {
        __syncthreads();   // (1) prev PV reads done
#pragma unroll
        for (int j = 0; j < 8; ++j)
            *(uint4*)&KVu[srow[j] * KST + scol[j]] = kreg[j];
        __syncthreads();   // (2) K visible

        uint4 vreg[8];
#pragma unroll
        for (int j = 0; j < 8; ++j)
            vreg[j] = *(const uint4*)(g_vt + (size_t)(t0 + srow[j]) * DIM + h * HD + scol[j]);

        // S = Q K^T : warp tile 32(q) x 16(kv)
        float Sacc[2][2][4] = {};
#pragma unroll
        for (int ks = 0; ks < 16; ++ks) {
            const int kb = ks * 8;
            uint32_t af[2][4], bf[2][2];
#pragma unroll
            for (int mt = 0; mt < 2; ++mt) {
                uint32_t addr = Qa + 4u * ((wm * 32 + mt * 16 + a_row) * QST + kb + a_ko);
                ldsm_x4(af[mt][0], af[mt][1], af[mt][2], af[mt][3], addr);
            }
            {
                uint32_t addr = Ka + 4u * ((wn * 16 + b_row) * KST + kb + b_ko);
                ldsm_x4(bf[0][0], bf[0][1], bf[1][0], bf[1][1], addr);
            }
#pragma unroll
            for (int mt = 0; mt < 2; ++mt)
#pragma unroll
                for (int nt = 0; nt < 2; ++nt)
                    mma_tf32(Sacc[mt][nt],
                             af[mt][0], af[mt][1], af[mt][2], af[mt][3],
                             bf[nt][0], bf[nt][1]);
        }
#pragma unroll
        for (int mt = 0; mt < 2; ++mt) {
            int r = wm * 32 + mt * 16 + (lane >> 2);
#pragma unroll
            for (int nt = 0; nt < 2; ++nt) {
                int c = wn * 16 + nt * 8 + (lane & 3) * 2;
                *(float2*)&Ss[r * SST + c] = make_float2(Sacc[mt][nt][0], Sacc[mt][nt][1]);
                *(float2*)&Ss[(r + 8) * SST + c] = make_float2(Sacc[mt][nt][2], Sacc[mt][nt][3]);
            }
        }

        if (t0 + FK < LTOK) {
#pragma unroll
            for (int j = 0; j < 8; ++j)
                kreg[j] = *(const uint4*)(g_kt + (size_t)(t0 + FK + srow[j]) * DIM + h * HD + scol[j]);
        }
        __syncthreads();   // (3) Ss visible, KVs free

#pragma unroll
        for (int j = 0; j < 8; ++j)
            *(uint4*)&KVu[srow[j] * VST + scol[j]] = vreg[j];

        // online softmax (column-interleaved per seg)
        {
            const int row = tid >> 2;
            const int seg = tid & 3;
            const float mold = m_s[row];
            float vals[16];
            float tm = -3.0e38f;
#pragma unroll
            for (int c = 0; c < 16; ++c) {
                vals[c] = Ss[row * SST + seg + 4 * c];
                tm = fmaxf(tm, vals[c]);
            }
            tm = fmaxf(tm, __shfl_xor_sync(0xffffffffu, tm, 1));
            tm = fmaxf(tm, __shfl_xor_sync(0xffffffffu, tm, 2));
            const float mnew = fmaxf(mold, tm);
            float psum = 0.f;
#pragma unroll
            for (int c = 0; c < 16; ++c) {
                float p = __expf(vals[c] - mnew);
                psum += p;
                Su[row * SST + seg + 4 * c] = f2tf(p);
            }
            psum += __shfl_xor_sync(0xffffffffu, psum, 1);
            psum += __shfl_xor_sync(0xffffffffu, psum, 2);
            if (seg == 0) {
                float f = __expf(mold - mnew);
                f_s[row] = f;
                l_s[row] = l_s[row] * f + psum;
                m_s[row] = mnew;
            }
        }
        __syncthreads();   // (4) V + Su + f_s visible

        // O = O*f + P @ V : warp tile 32(q) x 32(hd)
#pragma unroll
        for (int mt = 0; mt < 2; ++mt) {
            int r = wm * 32 + mt * 16 + (lane >> 2);
            float f0 = f_s[r], f1 = f_s[r + 8];
#pragma unroll
            for (int nt = 0; nt < 4; ++nt) {
                O[mt * 4 + nt][0] *= f0; O[mt * 4 + nt][1] *= f0;
                O[mt * 4 + nt][2] *= f1; O[mt * 4 + nt][3] *= f1;
            }
        }
#pragma unroll
        for (int ks = 0; ks < 8; ++ks) {
            const int kb = ks * 8;
            uint32_t af[2][4], bf[4][2];
#pragma unroll
            for (int mt = 0; mt < 2; ++mt) {
                uint32_t addr = Sa + 4u * ((wm * 32 + mt * 16 + a_row) * SST + kb + a_ko);
                ldsm_x4(af[mt][0], af[mt][1], af[mt][2], af[mt][3], addr);
            }
#pragma unroll
            for (int nt = 0; nt < 4; ++nt) {
                int c = wn * 32 + nt * 8 + (lane >> 2);
                bf[nt][0] = KVu[(kb + (lane & 3)) * VST + c];
                bf[nt][1] = KVu[(kb + (lane & 3) + 4) * VST + c];
            }
#pragma unroll
            for (int mt = 0; mt < 2; ++mt)
#pragma unroll
                for (int nt = 0; nt < 4; ++nt)
                    mma_tf32(O[mt * 4 + nt],
                             af[mt][0], af[mt][1], af[mt][2], af[mt][3],
                             bf[nt][0], bf[nt][1]);
        }
    }

    // finalize
#pragma unroll
    for (int mt = 0; mt < 2; ++mt) {
        int r = wm * 32 + mt * 16 + (lane >> 2);
        float inv0 = 1.f / l_s[r], inv1 = 1.f / l_s[r + 8];
#pragma unroll
        for (int nt = 0; nt < 4; ++nt) {
            int c = wn * 32 + nt * 8 + (lane & 3) * 2;
            float* d0 = g_o + (size_t)(q0 + r) * DIM + h * HD + c;
            *(float2*)d0 = make_float2(O[mt * 4 + nt][0] * inv0, O[mt * 4 + nt][1] * inv0);
            float* d1 = g_o + (size_t)(q0 + r + 8) * DIM + h * HD + c;
            *(float2*)d1 = make_float2(O[mt * 4 + nt][2] * inv1, O[mt * 4 + nt][3] * inv1);
        }
    }
}

// ================= launch =================
extern "C" void kernel_launch(void* const* d_in, const int* in_sizes, int n_in,
                              void* d_out, int out_size)
{
    const float* x          = (const float*)d_in[0];
    const int*   grid_sizes = (const int*)d_in[2];
    const float* freqs      = (const float*)d_in[3];
    const float* Wq = (const float*)d_in[4];
    const float* bq = (const float*)d_in[5];
    const float* Wk = (const float*)d_in[6];
    const float* bk = (const float*)d_in[7];
    const float* Wv = (const float*)d_in[8];
    const float* bv = (const float*)d_in[9];
    const float* Wo = (const float*)d_in[10];
    const float* bo = (const float*)d_in[11];
    const float* gq = (const float*)d_in[12];
    const float* gk = (const float*)d_in[13];
    float* out = (float*)d_out;

    uint32_t *xt, *wt, *ot, *vt;
    float *op, *vp;
    cudaGetSymbolAddress((void**)&xt, g_xt);
    cudaGetSymbolAddress((void**)&wt, g_wt);
    cudaGetSymbolAddress((void**)&ot, g_ot);
    cudaGetSymbolAddress((void**)&vt, g_vt);
    cudaGetSymbolAddress((void**)&op, g_o);
    cudaGetSymbolAddress((void**)&vp, g_v);

    const int flash_smem = FLASH_SMEM_FLOATS * sizeof(float);
    cudaFuncSetAttribute(flash_tf32, cudaFuncAttributeMaxDynamicSharedMemorySize, flash_smem);
    cudaFuncSetAttribute(qkv_gemm_tf32, cudaFuncAttributeMaxDynamicSharedMemorySize, GM_SMEM_BYTES);
    cudaFuncSetAttribute(out_gemm_tf32, cudaFuncAttributeMaxDynamicSharedMemorySize, GM_SMEM_BYTES);

    const int NX4 = LTOK * DIM / 4;
    const int NW4 = DIM * DIM / 4;

    // pre-convert x and weights to tf32
    convert_tf32<<<(NX4 + 255) / 256, 256>>>((const float4*)x,  (uint4*)xt, NX4);
    convert_tf32<<<(NW4 + 255) / 256, 256>>>((const float4*)Wq, (uint4*)(wt + 0 * (size_t)DIM * DIM), NW4);
    convert_tf32<<<(NW4 + 255) / 256, 256>>>((const float4*)Wk, (uint4*)(wt + 1 * (size_t)DIM * DIM), NW4);
    convert_tf32<<<(NW4 + 255) / 256, 256>>>((const float4*)Wv, (uint4*)(wt + 2 * (size_t)DIM * DIM), NW4);
    convert_tf32<<<(NW4 + 255) / 256, 256>>>((const float4*)Wo, (uint4*)(wt + 3 * (size_t)DIM * DIM), NW4);

    dim3 gqkv(DIM / GM_BN, (LTOK + GM_BM - 1) / GM_BM, 3);   // 12 x 28 x 3
    dim3 gout(DIM / GM_BN, (LTOK + GM_BM - 1) / GM_BM);      // 12 x 28

    qkv_gemm_tf32<<<gqkv, 256, GM_SMEM_BYTES>>>(bq, bk, bv);
    rmsnorm_rope<<<dim3(LTOK, 2), 256>>>(gq, gk, freqs, grid_sizes);
    convert_tf32<<<(NX4 + 255) / 256, 256>>>((const float4*)vp, (uint4*)vt, NX4);
    flash_tf32<<<dim3(LTOK / FQ, HEADS), 256, flash_smem>>>();
    convert_tf32<<<(NX4 + 255) / 256, 256>>>((const float4*)op, (uint4*)ot, NX4);
    out_gemm_tf32<<<gout, 256, GM_SMEM_BYTES>>>(bo, out);
}

// round 12
// speedup vs baseline: 1.9213x; 1.7463x over previous
#include <cuda_runtime.h>
#include <cuda_fp16.h>
#include <cstdint>

#define DIM    1536
#define HEADS  12
#define HD     128
#define LTOK   3520
#define EPS    1e-6f
#define SCALE  0.08838834764831845f   // 1/sqrt(128)
#define LOG2E  1.4426950408889634f

// ---------------- scratch (no allocation allowed) ----------------
__device__ float  g_q[LTOK * DIM];
__device__ float  g_k[LTOK * DIM];
__device__ float  g_v[LTOK * DIM];
__device__ __half g_xt[LTOK * DIM];
__device__ __half g_wt[4][DIM * DIM];
__device__ __half g_qt[LTOK * DIM];   // rmsnorm+rope q, *SCALE*log2e
__device__ __half g_kt[LTOK * DIM];   // rmsnorm+rope k
__device__ __half g_vt[LTOK * DIM];   // v
__device__ __half g_ot[LTOK * DIM];   // attention output

// ---------------- helpers ----------------
__device__ __forceinline__ void mma_f16(float c[4],
    uint32_t a0, uint32_t a1, uint32_t a2, uint32_t a3,
    uint32_t b0, uint32_t b1)
{
    asm volatile(
        "mma.sync.aligned.m16n8k16.row.col.f32.f16.f16.f32 "
        "{%0,%1,%2,%3}, {%4,%5,%6,%7}, {%8,%9}, {%0,%1,%2,%3};\n"
        : "+f"(c[0]), "+f"(c[1]), "+f"(c[2]), "+f"(c[3])
        : "r"(a0), "r"(a1), "r"(a2), "r"(a3), "r"(b0), "r"(b1));
}
__device__ __forceinline__ void ldsm_x4(uint32_t& r0, uint32_t& r1,
                                        uint32_t& r2, uint32_t& r3, uint32_t addr)
{
    asm volatile("ldmatrix.sync.aligned.m8n8.x4.shared.b16 {%0,%1,%2,%3}, [%4];"
                 : "=r"(r0), "=r"(r1), "=r"(r2), "=r"(r3) : "r"(addr));
}
__device__ __forceinline__ void ldsm_x4_t(uint32_t& r0, uint32_t& r1,
                                          uint32_t& r2, uint32_t& r3, uint32_t addr)
{
    asm volatile("ldmatrix.sync.aligned.m8n8.x4.trans.shared.b16 {%0,%1,%2,%3}, [%4];"
                 : "=r"(r0), "=r"(r1), "=r"(r2), "=r"(r3) : "r"(addr));
}
__device__ __forceinline__ uint32_t smem_addr(const void* p) {
    return (uint32_t)__cvta_generic_to_shared(p);
}
__device__ __forceinline__ void cp_async16(uint32_t dst, const void* src) {
    asm volatile("cp.async.cg.shared.global [%0], [%1], 16;" :: "r"(dst), "l"(src));
}
#define CP_COMMIT() asm volatile("cp.async.commit_group;" ::: "memory")
#define CP_WAIT1()  asm volatile("cp.async.wait_group 1;" ::: "memory")

// ================= fp16 convert kernel (gmem -> gmem) =================
__global__ void __launch_bounds__(256) convert_f16(const float4* __restrict__ src,
                                                   uint2* __restrict__ dst, int n4)
{
    int i = blockIdx.x * blockDim.x + threadIdx.x;
    if (i < n4) {
        float4 v = src[i];
        __half2 lo = __floats2half2_rn(v.x, v.y);
        __half2 hi = __floats2half2_rn(v.z, v.w);
        dst[i] = make_uint2(*(uint32_t*)&lo, *(uint32_t*)&hi);
    }
}

// ================= fp16 GEMM: C[M,N] = A[M,K] @ B[N,K]^T + bias ==========
// BM=BN=128, BK=32 halves, 256 threads (8 warps 2x4), warp tile 64x32.
// 3-stage cp.async ring, 1 barrier per K-iter. m16n8k16.
#define GM_BM 128
#define GM_BN 128
#define GM_BK 32
#define GSTR_H 40                         // row stride halves (80B = 5*16B)
#define GM_TILE_H (GM_BM * GSTR_H)
#define GM_STAGE_H (2 * GM_TILE_H)
#define GM_SMEM_BYTES (3 * GM_STAGE_H * 2)   // 61440

__device__ __forceinline__ void gemm_tile_f16(
    const __half* __restrict__ A, const __half* __restrict__ B,
    const float* __restrict__ bias, float* __restrict__ C,
    int M, int N, int K, int m0, int n0, __half* sm)
{
    const int tid = threadIdx.x;
    const int lane = tid & 31;
    const int wid = tid >> 5;
    const int wm = wid >> 2;
    const int wn = wid & 3;

    const int tr = lane & 7;
    const int mq = lane >> 3;
    const int a_row = tr + 8 * (mq & 1);
    const int a_kb  = 16 * (mq >> 1);     // byte offset: k half
    const int b_row = tr + 8 * (mq >> 1);
    const int b_kb  = 16 * (mq & 1);

    const int kc = (tid & 3) * 8;         // half offset within BK=32 row
    int sr[4], arow[4], brow[4];
#pragma unroll
    for (int i = 0; i < 4; ++i) {
        int s = tid + i * 256;
        sr[i]  = s >> 2;                  // 0..255 -> rows 0..127 twice? no: 1024/4
        arow[i] = 0; brow[i] = 0;
    }
    // staging: 2 chunks per tile per thread (A) + 2 (B): s = tid + i*256, i<2
    int r2[2], kc2[2];
#pragma unroll
    for (int i = 0; i < 2; ++i) {
        int s = tid + i * 256;
        r2[i] = s >> 2;                   // 0..127
        kc2[i] = (s & 3) * 8;             // 0,8,16,24 halves
        arow[i] = min(m0 + r2[i], M - 1);
        brow[i] = n0 + r2[i];
    }

    const uint32_t smu = smem_addr(sm);

    auto fill = [&](int st, int k0) {
        const uint32_t base = smu + 2u * (st * GM_STAGE_H);
#pragma unroll
        for (int i = 0; i < 2; ++i)
            cp_async16(base + 2u * (r2[i] * GSTR_H + kc2[i]),
                       A + (size_t)arow[i] * K + k0 + kc2[i]);
#pragma unroll
        for (int i = 0; i < 2; ++i)
            cp_async16(base + 2u * (GM_TILE_H + r2[i] * GSTR_H + kc2[i]),
                       B + (size_t)brow[i] * K + k0 + kc2[i]);
        CP_COMMIT();
    };

    fill(0, 0);
    fill(1, GM_BK);

    float acc[16][4];
#pragma unroll
    for (int t = 0; t < 16; ++t)
        acc[t][0] = acc[t][1] = acc[t][2] = acc[t][3] = 0.f;

    const int NIT = K / GM_BK;   // 48
    int st = 0;
    for (int it = 0; it < NIT; ++it) {
        CP_WAIT1();
        __syncthreads();
        if (it + 2 < NIT) fill((st + 2) % 3, (it + 2) * GM_BK);
        else CP_COMMIT();

        const uint32_t Ab = smu + 2u * (st * GM_STAGE_H);
        const uint32_t Bb = Ab + 2u * GM_TILE_H;
#pragma unroll
        for (int ks = 0; ks < 2; ++ks) {
            const int kbb = ks * 32;     // bytes (16 halves)
            uint32_t af[4][4], bf[4][2];
#pragma unroll
            for (int mt = 0; mt < 4; ++mt) {
                uint32_t addr = Ab + (wm * 64 + mt * 16 + a_row) * (GSTR_H * 2) + kbb + a_kb;
                ldsm_x4(af[mt][0], af[mt][1], af[mt][2], af[mt][3], addr);
            }
#pragma unroll
            for (int p = 0; p < 2; ++p) {
                uint32_t addr = Bb + (wn * 32 + p * 16 + b_row) * (GSTR_H * 2) + kbb + b_kb;
                ldsm_x4(bf[2*p][0], bf[2*p][1], bf[2*p+1][0], bf[2*p+1][1], addr);
            }
#pragma unroll
            for (int mt = 0; mt < 4; ++mt)
#pragma unroll
                for (int nt = 0; nt < 4; ++nt)
                    mma_f16(acc[mt * 4 + nt],
                            af[mt][0], af[mt][1], af[mt][2], af[mt][3],
                            bf[nt][0], bf[nt][1]);
        }
        st = (st + 1) % 3;
    }

    // epilogue
#pragma unroll
    for (int nt = 0; nt < 4; ++nt) {
        int c = n0 + wn * 32 + nt * 8 + (lane & 3) * 2;
        float b0 = bias[c], b1 = bias[c + 1];
#pragma unroll
        for (int mt = 0; mt < 4; ++mt) {
            int r = m0 + wm * 64 + mt * 16 + (lane >> 2);
            float* a4 = acc[mt * 4 + nt];
            if (r < M)
                *(float2*)(C + (size_t)r * N + c) = make_float2(a4[0] + b0, a4[1] + b1);
            if (r + 8 < M)
                *(float2*)(C + (size_t)(r + 8) * N + c) = make_float2(a4[2] + b0, a4[3] + b1);
        }
    }
}

__global__ void __launch_bounds__(256, 2) qkv_gemm_f16(
    const float* __restrict__ bq, const float* __restrict__ bk,
    const float* __restrict__ bv)
{
    extern __shared__ __align__(16) __half smh[];
    const float* b; float* out;
    if (blockIdx.z == 0)      { b = bq; out = g_q; }
    else if (blockIdx.z == 1) { b = bk; out = g_k; }
    else                      { b = bv; out = g_v; }
    gemm_tile_f16(g_xt, g_wt[blockIdx.z], b, out, LTOK, DIM, DIM,
                  blockIdx.y * GM_BM, blockIdx.x * GM_BN, smh);
}

__global__ void __launch_bounds__(256, 2) out_gemm_f16(
    const float* __restrict__ bo, float* __restrict__ out)
{
    extern __shared__ __align__(16) __half smh[];
    gemm_tile_f16(g_ot, g_wt[3], bo, out, LTOK, DIM, DIM,
                  blockIdx.y * GM_BM, blockIdx.x * GM_BN, smh);
}

// ============ fused RMSNorm + RoPE -> fp16 outputs (q pre-scaled) ========
__global__ void __launch_bounds__(256) rmsnorm_rope(
    const float* __restrict__ gq, const float* __restrict__ gk,
    const float* __restrict__ freqs, const int* __restrict__ gsz)
{
    const int t = blockIdx.x;
    const int which = blockIdx.y;
    const float* row = (which ? g_k : g_q) + (size_t)t * DIM;
    __half* rowo = (which ? g_kt : g_qt) + (size_t)t * DIM;
    const float oscale = which ? 1.0f : (SCALE * LOG2E);
    const float* g = which ? gk : gq;
    const int tid = threadIdx.x;

    float ss = 0.f;
    for (int i = tid; i < DIM; i += 256) {
        float v = row[i];
        ss += v * v;
    }
    __shared__ float red[8];
#pragma unroll
    for (int o = 16; o; o >>= 1) ss += __shfl_xor_sync(0xffffffffu, ss, o);
    if ((tid & 31) == 0) red[tid >> 5] = ss;
    __syncthreads();
    if (tid < 8) {
        float v = red[tid];
#pragma unroll
        for (int o = 4; o; o >>= 1) v += __shfl_xor_sync(0xffu, v, o);
        if (tid == 0) red[0] = v;
    }
    __syncthreads();
    const float rms = rsqrtf(red[0] * (1.0f / DIM) + EPS);

    const int Hs = gsz[1], Ws = gsz[2];
    const int fi = t / (Hs * Ws);
    const int hi = (t / Ws) % Hs;
    const int wi = t % Ws;

    for (int p = tid; p < HEADS * 64; p += 256) {
        const int h = p >> 6;
        const int j = p & 63;
        const int pos = (j < 22) ? fi : ((j < 43) ? hi : wi);
        const float ang = freqs[pos * 64 + j];
        float c, s;
        sincosf(ang, &s, &c);
        const int d0 = h * HD + 2 * j;
        const float x0 = row[d0]     * rms * g[d0];
        const float x1 = row[d0 + 1] * rms * g[d0 + 1];
        __half2 o = __floats2half2_rn((x0 * c - x1 * s) * oscale,
                                      (x0 * s + x1 * c) * oscale);
        *(__half2*)(rowo + d0) = o;
    }
}

// ====== flash attention (fp16 mma m16n8k16, exp2-domain softmax) ========
#define FQ 64
#define FK 64
#define QST_H 136     // 272B rows; bank step 4 -> conflict-free ldsm
#define KST_H 136
#define VST_H 136
#define SST_H 72      // 144B rows
#define FLASH_SMEM_BYTES (FQ*QST_H*2 + FK*KST_H*2 + FQ*SST_H*2 + 3*FQ*4)

__global__ void __launch_bounds__(256, 2) flash_f16()
{
    extern __shared__ __align__(16) char smc[];
    __half* Qs  = (__half*)smc;
    __half* KVs = Qs + FQ * QST_H;
    __half* Ss  = KVs + FK * KST_H;
    float* m_s = (float*)(Ss + FQ * SST_H);
    float* l_s = m_s + FQ;
    float* f_s = l_s + FQ;

    const int tid = threadIdx.x;
    const int lane = tid & 31;
    const int wid = tid >> 5;
    const int wm = wid >> 2;
    const int wn = wid & 3;
    const int h  = blockIdx.y;
    const int q0 = blockIdx.x * FQ;

    const int tr = lane & 7;
    const int mq = lane >> 3;
    const int a_row = tr + 8 * (mq & 1);
    const int a_kb  = 16 * (mq >> 1);
    const int b_row = tr + 8 * (mq >> 1);
    const int b_kb  = 16 * (mq & 1);
    // trans ldsm (V): matrix mq -> k-half (mq&1), n-half (mq>>1)
    const int v_krow = tr + 8 * (mq & 1);
    const int v_noff = 8 * (mq >> 1);

    const uint32_t Qa = smem_addr(Qs);
    const uint32_t Ka = smem_addr(KVs);
    const uint32_t Sa = smem_addr(Ss);

    // staging: 4 uint4 per tile per thread (64 rows x 128 halves)
    int srow[4], scol[4];
#pragma unroll
    for (int j = 0; j < 4; ++j) {
        int i = tid + j * 256;
        srow[j] = i >> 4;
        scol[j] = (i & 15) * 8;
    }

    // Q tile (pre-scaled fp16)
#pragma unroll
    for (int j = 0; j < 4; ++j) {
        uint4 v = *(const uint4*)(g_qt + (size_t)(q0 + srow[j]) * DIM + h * HD + scol[j]);
        *(uint4*)&Qs[srow[j] * QST_H + scol[j]] = v;
    }
    if (tid < FQ) { m_s[tid] = -3.0e38f; l_s[tid] = 0.f; }

    float O[8][4];
#pragma unroll
    for (int t = 0; t < 8; ++t) O[t][0] = O[t][1] = O[t][2] = O[t][3] = 0.f;

    uint4 kreg[4];
#pragma unroll
    for (int j = 0; j < 4; ++j)
        kreg[j] = *(const uint4*)(g_kt + (size_t)srow[j] * DIM + h * HD + scol[j]);

    for (int t0 = 0; t0 < LTOK; t0 += FK) {
        __syncthreads();   // (1) prev PV reads done
#pragma unroll
        for (int j = 0; j < 4; ++j)
            *(uint4*)&KVs[srow[j] * KST_H + scol[j]] = kreg[j];
        __syncthreads();   // (2) K visible

        uint4 vreg[4];
#pragma unroll
        for (int j = 0; j < 4; ++j)
            vreg[j] = *(const uint4*)(g_vt + (size_t)(t0 + srow[j]) * DIM + h * HD + scol[j]);

        // S = Q K^T (log2-domain; q pre-scaled): warp tile 32(q) x 16(kv)
        float Sacc[2][2][4] = {};
#pragma unroll
        for (int ks = 0; ks < 8; ++ks) {
            const int kbb = ks * 32;   // bytes (16 halves)
            uint32_t af[2][4], bf[2][2];
#pragma unroll
            for (int mt = 0; mt < 2; ++mt) {
                uint32_t addr = Qa + (wm * 32 + mt * 16 + a_row) * (QST_H * 2) + kbb + a_kb;
                ldsm_x4(af[mt][0], af[mt][1], af[mt][2], af[mt][3], addr);
            }
            {
                uint32_t addr = Ka + (wn * 16 + b_row) * (KST_H * 2) + kbb + b_kb;
                ldsm_x4(bf[0][0], bf[0][1], bf[1][0], bf[1][1], addr);
            }
#pragma unroll
            for (int mt = 0; mt < 2; ++mt)
#pragma unroll
                for (int nt = 0; nt < 2; ++nt)
                    mma_f16(Sacc[mt][nt],
                            af[mt][0], af[mt][1], af[mt][2], af[mt][3],
                            bf[nt][0], bf[nt][1]);
        }
#pragma unroll
        for (int mt = 0; mt < 2; ++mt) {
            int r = wm * 32 + mt * 16 + (lane >> 2);
#pragma unroll
            for (int nt = 0; nt < 2; ++nt) {
                int c = wn * 16 + nt * 8 + (lane & 3) * 2;
                // store fp32 S into Ss as float pairs? -> store as fp32 via half? keep fp32 in Ss:
                // Ss holds fp32 during softmax? No: Ss is half. Store rounded later in softmax.
                // Store raw S as float in a reinterpreted region is not possible (half tile).
                // Instead store fp16 S (10-bit) - acceptable: S in [-30,30] log2 units.
                *(__half2*)&Ss[r * SST_H + c] =
                    __floats2half2_rn(Sacc[mt][nt][0], Sacc[mt][nt][1]);
                *(__half2*)&Ss[(r + 8) * SST_H + c] =
                    __floats2half2_rn(Sacc[mt][nt][2], Sacc[mt][nt][3]);
            }
        }

        if (t0 + FK < LTOK) {
#pragma unroll
            for (int j = 0; j < 4; ++j)
                kreg[j] = *(const uint4*)(g_kt + (size_t)(t0 + FK + srow[j]) * DIM + h * HD + scol[j]);
        }
        __syncthreads();   // (3) Ss visible, KVs free

#pragma unroll
        for (int j = 0; j < 4; ++j)
            *(uint4*)&KVs[srow[j] * VST_H + scol[j]] = vreg[j];

        // online softmax in exp2 domain (column pair-interleaved per seg)
        {
            const int row = tid >> 2;
            const int seg = tid & 3;
            const float mold = m_s[row];
            float2 vals[8];
            float tm = -3.0e38f;
#pragma unroll
            for (int pc = 0; pc < 8; ++pc) {
                __half2 hv = *(__half2*)&Ss[row * SST_H + 2 * (seg + 4 * pc)];
                float2 fv = __half22float2(hv);
                vals[pc] = fv;
                tm = fmaxf(tm, fmaxf(fv.x, fv.y));
            }
            tm = fmaxf(tm, __shfl_xor_sync(0xffffffffu, tm, 1));
            tm = fmaxf(tm, __shfl_xor_sync(0xffffffffu, tm, 2));
            const float mnew = fmaxf(mold, tm);
            float psum = 0.f;
#pragma unroll
            for (int pc = 0; pc < 8; ++pc) {
                float p0 = exp2f(vals[pc].x - mnew);
                float p1 = exp2f(vals[pc].y - mnew);
                psum += p0 + p1;
                *(__half2*)&Ss[row * SST_H + 2 * (seg + 4 * pc)] = __floats2half2_rn(p0, p1);
            }
            psum += __shfl_xor_sync(0xffffffffu, psum, 1);
            psum += __shfl_xor_sync(0xffffffffu, psum, 2);
            if (seg == 0) {
                float f = exp2f(mold - mnew);
                f_s[row] = f;
                l_s[row] = l_s[row] * f + psum;
                m_s[row] = mnew;
            }
        }
        __syncthreads();   // (4) V + P + f_s visible

        // O = O*f + P @ V : warp tile 32(q) x 32(hd)
#pragma unroll
        for (int mt = 0; mt < 2; ++mt) {
            int r = wm * 32 + mt * 16 + (lane >> 2);
            float f0 = f_s[r], f1 = f_s[r + 8];
#pragma unroll
            for (int nt = 0; nt < 4; ++nt) {
                O[mt * 4 + nt][0] *= f0; O[mt * 4 + nt][1] *= f0;
                O[mt * 4 + nt][2] *= f1; O[mt * 4 + nt][3] *= f1;
            }
        }
        const uint32_t Va = Ka;   // V shares KV buffer
#pragma unroll
        for (int ks = 0; ks < 4; ++ks) {
            const int kb = ks * 16;       // k tokens
            uint32_t af[2][4], bf[4][2];
#pragma unroll
            for (int mt = 0; mt < 2; ++mt) {
                uint32_t addr = Sa + (wm * 32 + mt * 16 + a_row) * (SST_H * 2) + ks * 32 + a_kb;
                ldsm_x4(af[mt][0], af[mt][1], af[mt][2], af[mt][3], addr);
            }
#pragma unroll
            for (int p = 0; p < 2; ++p) {
                int c0 = wn * 32 + p * 16;
                uint32_t addr = Va + (kb + v_krow) * (VST_H * 2) + (c0 + v_noff) * 2;
                ldsm_x4_t(bf[2*p][0], bf[2*p][1], bf[2*p+1][0], bf[2*p+1][1], addr);
            }
#pragma unroll
            for (int mt = 0; mt < 2; ++mt)
#pragma unroll
                for (int nt = 0; nt < 4; ++nt)
                    mma_f16(O[mt * 4 + nt],
                            af[mt][0], af[mt][1], af[mt][2], af[mt][3],
                            bf[nt][0], bf[nt][1]);
        }
    }

    // finalize -> fp16 g_ot
#pragma unroll
    for (int mt = 0; mt < 2; ++mt) {
        int r = wm * 32 + mt * 16 + (lane >> 2);
        float inv0 = 1.f / l_s[r], inv1 = 1.f / l_s[r + 8];
#pragma unroll
        for (int nt = 0; nt < 4; ++nt) {
            int c = wn * 32 + nt * 8 + (lane & 3) * 2;
            float* a4 = O[mt * 4 + nt];
            *(__half2*)(g_ot + (size_t)(q0 + r) * DIM + h * HD + c) =
                __floats2half2_rn(a4[0] * inv0, a4[1] * inv0);
            *(__half2*)(g_ot + (size_t)(q0 + r + 8) * DIM + h * HD + c) =
                __floats2half2_rn(a4[2] * inv1, a4[3] * inv1);
        }
    }
}

// ================= launch =================
extern "C" void kernel_launch(void* const* d_in, const int* in_sizes, int n_in,
                              void* d_out, int out_size)
{
    const float* x          = (const float*)d_in[0];
    const int*   grid_sizes = (const int*)d_in[2];
    const float* freqs      = (const float*)d_in[3];
    const float* Wq = (const float*)d_in[4];
    const float* bq = (const float*)d_in[5];
    const float* Wk = (const float*)d_in[6];
    const float* bk = (const float*)d_in[7];
    const float* Wv = (const float*)d_in[8];
    const float* bv = (const float*)d_in[9];
    const float* Wo = (const float*)d_in[10];
    const float* bo = (const float*)d_in[11];
    const float* gq = (const float*)d_in[12];
    const float* gk = (const float*)d_in[13];
    float* out = (float*)d_out;

    __half *xt, *wt, *vt;
    float* vp;
    cudaGetSymbolAddress((void**)&xt, g_xt);
    cudaGetSymbolAddress((void**)&wt, g_wt);
    cudaGetSymbolAddress((void**)&vt, g_vt);
    cudaGetSymbolAddress((void**)&vp, g_v);

    cudaFuncSetAttribute(flash_f16, cudaFuncAttributeMaxDynamicSharedMemorySize, FLASH_SMEM_BYTES);
    cudaFuncSetAttribute(qkv_gemm_f16, cudaFuncAttributeMaxDynamicSharedMemorySize, GM_SMEM_BYTES);
    cudaFuncSetAttribute(out_gemm_f16, cudaFuncAttributeMaxDynamicSharedMemorySize, GM_SMEM_BYTES);

    const int NX4 = LTOK * DIM / 4;
    const int NW4 = DIM * DIM / 4;

    convert_f16<<<(NX4 + 255) / 256, 256>>>((const float4*)x,  (uint2*)xt, NX4);
    convert_f16<<<(NW4 + 255) / 256, 256>>>((const float4*)Wq, (uint2*)(wt + 0 * (size_t)DIM * DIM), NW4);
    convert_f16<<<(NW4 + 255) / 256, 256>>>((const float4*)Wk, (uint2*)(wt + 1 * (size_t)DIM * DIM), NW4);
    convert_f16<<<(NW4 + 255) / 256, 256>>>((const float4*)Wv, (uint2*)(wt + 2 * (size_t)DIM * DIM), NW4);
    convert_f16<<<(NW4 + 255) / 256, 256>>>((const float4*)Wo, (uint2*)(wt + 3 * (size_t)DIM * DIM), NW4);

    dim3 gqkv(DIM / GM_BN, (LTOK + GM_BM - 1) / GM_BM, 3);   // 12 x 28 x 3
    dim3 gout(DIM / GM_BN, (LTOK + GM_BM - 1) / GM_BM);      // 12 x 28

    qkv_gemm_f16<<<gqkv, 256, GM_SMEM_BYTES>>>(bq, bk, bv);
    rmsnorm_rope<<<dim3(LTOK, 2), 256>>>(gq, gk, freqs, grid_sizes);
    convert_f16<<<(NX4 + 255) / 256, 256>>>((const float4*)vp, (uint2*)vt, NX4);
    flash_f16<<<dim3(LTOK / FQ, HEADS), 256, FLASH_SMEM_BYTES>>>();
    out_gemm_f16<<<gout, 256, GM_SMEM_BYTES>>>(bo, out);
}

// round 13
// speedup vs baseline: 1.9423x; 1.0110x over previous
#include <cuda_runtime.h>
#include <cuda_fp16.h>
#include <cstdint>

#define DIM    1536
#define HEADS  12
#define HD     128
#define LTOK   3520
#define EPS    1e-6f
#define SCALE  0.08838834764831845f   // 1/sqrt(128)
#define LOG2E  1.4426950408889634f

// ---------------- scratch (no allocation allowed) ----------------
__device__ float  g_q[LTOK * DIM];
__device__ float  g_k[LTOK * DIM];
__device__ float  g_v[LTOK * DIM];
__device__ __half g_xt[LTOK * DIM];
__device__ __half g_wt[4][DIM * DIM];
__device__ __half g_qt[LTOK * DIM];   // rmsnorm+rope q, *SCALE*log2e
__device__ __half g_kt[LTOK * DIM];   // rmsnorm+rope k
__device__ __half g_vt[LTOK * DIM];   // v
__device__ __half g_ot[LTOK * DIM];   // attention output

// ---------------- helpers ----------------
__device__ __forceinline__ void mma_f16(float c[4],
    uint32_t a0, uint32_t a1, uint32_t a2, uint32_t a3,
    uint32_t b0, uint32_t b1)
{
    asm volatile(
        "mma.sync.aligned.m16n8k16.row.col.f32.f16.f16.f32 "
        "{%0,%1,%2,%3}, {%4,%5,%6,%7}, {%8,%9}, {%0,%1,%2,%3};\n"
        : "+f"(c[0]), "+f"(c[1]), "+f"(c[2]), "+f"(c[3])
        : "r"(a0), "r"(a1), "r"(a2), "r"(a3), "r"(b0), "r"(b1));
}
__device__ __forceinline__ void ldsm_x4(uint32_t& r0, uint32_t& r1,
                                        uint32_t& r2, uint32_t& r3, uint32_t addr)
{
    asm volatile("ldmatrix.sync.aligned.m8n8.x4.shared.b16 {%0,%1,%2,%3}, [%4];"
                 : "=r"(r0), "=r"(r1), "=r"(r2), "=r"(r3) : "r"(addr));
}
__device__ __forceinline__ void ldsm_x4_t(uint32_t& r0, uint32_t& r1,
                                          uint32_t& r2, uint32_t& r3, uint32_t addr)
{
    asm volatile("ldmatrix.sync.aligned.m8n8.x4.trans.shared.b16 {%0,%1,%2,%3}, [%4];"
                 : "=r"(r0), "=r"(r1), "=r"(r2), "=r"(r3) : "r"(addr));
}
__device__ __forceinline__ uint32_t smem_addr(const void* p) {
    return (uint32_t)__cvta_generic_to_shared(p);
}
__device__ __forceinline__ void cp_async16(uint32_t dst, const void* src) {
    asm volatile("cp.async.cg.shared.global [%0], [%1], 16;" :: "r"(dst), "l"(src));
}
#define CP_COMMIT() asm volatile("cp.async.commit_group;" ::: "memory")
#define CP_WAIT1()  asm volatile("cp.async.wait_group 1;" ::: "memory")

// ================= fp16 convert kernel (gmem -> gmem) =================
__global__ void __launch_bounds__(256) convert_f16(const float4* __restrict__ src,
                                                   uint2* __restrict__ dst, int n4)
{
    int i = blockIdx.x * blockDim.x + threadIdx.x;
    if (i < n4) {
        float4 v = src[i];
        __half2 lo = __floats2half2_rn(v.x, v.y);
        __half2 hi = __floats2half2_rn(v.z, v.w);
        dst[i] = make_uint2(*(uint32_t*)&lo, *(uint32_t*)&hi);
    }
}

// ================= fp16 GEMM: C[M,N] = A[M,K] @ B[N,K]^T + bias ==========
// BM=BN=128, BK=64 halves, 256 threads (8 warps 2x4), warp tile 64x32.
// 3-stage cp.async ring, 1 barrier per K-iter (24 iters). m16n8k16.
#define GM_BM 128
#define GM_BN 128
#define GM_BK 64
#define GSTR_H 72                         // row stride halves (144B = 9*16B)
#define GM_TILE_H (GM_BM * GSTR_H)
#define GM_STAGE_H (2 * GM_TILE_H)
#define GM_SMEM_BYTES (3 * GM_STAGE_H * 2)   // 110592

__device__ __forceinline__ void gemm_tile_f16(
    const __half* __restrict__ A, const __half* __restrict__ B,
    const float* __restrict__ bias, float* __restrict__ C,
    int M, int N, int K, int m0, int n0, __half* sm)
{
    const int tid = threadIdx.x;
    const int lane = tid & 31;
    const int wid = tid >> 5;
    const int wm = wid >> 2;
    const int wn = wid & 3;

    const int tr = lane & 7;
    const int mq = lane >> 3;
    const int a_row = tr + 8 * (mq & 1);
    const int a_kb  = 16 * (mq >> 1);     // byte offset: k half
    const int b_row = tr + 8 * (mq >> 1);
    const int b_kb  = 16 * (mq & 1);

    // staging: 4 chunks of 16B per operand per thread (128 rows x 64 halves)
    int r2[4], kc2[4], arow[4], brow[4];
#pragma unroll
    for (int i = 0; i < 4; ++i) {
        int s = tid + i * 256;
        r2[i] = s >> 3;                   // 0..127
        kc2[i] = (s & 7) * 8;             // 0..56 halves
        arow[i] = min(m0 + r2[i], M - 1);
        brow[i] = n0 + r2[i];
    }

    const uint32_t smu = smem_addr(sm);

    auto fill = [&](int st, int k0) {
        const uint32_t base = smu + 2u * (st * GM_STAGE_H);
#pragma unroll
        for (int i = 0; i < 4; ++i)
            cp_async16(base + 2u * (r2[i] * GSTR_H + kc2[i]),
                       A + (size_t)arow[i] * K + k0 + kc2[i]);
#pragma unroll
        for (int i = 0; i < 4; ++i)
            cp_async16(base + 2u * (GM_TILE_H + r2[i] * GSTR_H + kc2[i]),
                       B + (size_t)brow[i] * K + k0 + kc2[i]);
        CP_COMMIT();
    };

    fill(0, 0);
    fill(1, GM_BK);

    float acc[16][4];
#pragma unroll
    for (int t = 0; t < 16; ++t)
        acc[t][0] = acc[t][1] = acc[t][2] = acc[t][3] = 0.f;

    const int NIT = K / GM_BK;   // 24
    int st = 0;
    for (int it = 0; it < NIT; ++it) {
        CP_WAIT1();
        __syncthreads();
        if (it + 2 < NIT) fill((st + 2) % 3, (it + 2) * GM_BK);
        else CP_COMMIT();

        const uint32_t Ab = smu + 2u * (st * GM_STAGE_H);
        const uint32_t Bb = Ab + 2u * GM_TILE_H;
#pragma unroll
        for (int ks = 0; ks < 4; ++ks) {
            const int kbb = ks * 32;     // bytes (16 halves)
            uint32_t af[4][4], bf[4][2];
#pragma unroll
            for (int mt = 0; mt < 4; ++mt) {
                uint32_t addr = Ab + (wm * 64 + mt * 16 + a_row) * (GSTR_H * 2) + kbb + a_kb;
                ldsm_x4(af[mt][0], af[mt][1], af[mt][2], af[mt][3], addr);
            }
#pragma unroll
            for (int p = 0; p < 2; ++p) {
                uint32_t addr = Bb + (wn * 32 + p * 16 + b_row) * (GSTR_H * 2) + kbb + b_kb;
                ldsm_x4(bf[2*p][0], bf[2*p][1], bf[2*p+1][0], bf[2*p+1][1], addr);
            }
#pragma unroll
            for (int mt = 0; mt < 4; ++mt)
#pragma unroll
                for (int nt = 0; nt < 4; ++nt)
                    mma_f16(acc[mt * 4 + nt],
                            af[mt][0], af[mt][1], af[mt][2], af[mt][3],
                            bf[nt][0], bf[nt][1]);
        }
        st = (st + 1) % 3;
    }

    // epilogue
#pragma unroll
    for (int nt = 0; nt < 4; ++nt) {
        int c = n0 + wn * 32 + nt * 8 + (lane & 3) * 2;
        float b0 = bias[c], b1 = bias[c + 1];
#pragma unroll
        for (int mt = 0; mt < 4; ++mt) {
            int r = m0 + wm * 64 + mt * 16 + (lane >> 2);
            float* a4 = acc[mt * 4 + nt];
            if (r < M)
                *(float2*)(C + (size_t)r * N + c) = make_float2(a4[0] + b0, a4[1] + b1);
            if (r + 8 < M)
                *(float2*)(C + (size_t)(r + 8) * N + c) = make_float2(a4[2] + b0, a4[3] + b1);
        }
    }
}

__global__ void __launch_bounds__(256, 2) qkv_gemm_f16(
    const float* __restrict__ bq, const float* __restrict__ bk,
    const float* __restrict__ bv)
{
    extern __shared__ __align__(16) __half smh[];
    const float* b; float* out;
    if (blockIdx.z == 0)      { b = bq; out = g_q; }
    else if (blockIdx.z == 1) { b = bk; out = g_k; }
    else                      { b = bv; out = g_v; }
    gemm_tile_f16(g_xt, g_wt[blockIdx.z], b, out, LTOK, DIM, DIM,
                  blockIdx.y * GM_BM, blockIdx.x * GM_BN, smh);
}

__global__ void __launch_bounds__(256, 2) out_gemm_f16(
    const float* __restrict__ bo, float* __restrict__ out)
{
    extern __shared__ __align__(16) __half smh[];
    gemm_tile_f16(g_ot, g_wt[3], bo, out, LTOK, DIM, DIM,
                  blockIdx.y * GM_BM, blockIdx.x * GM_BN, smh);
}

// ============ fused RMSNorm + RoPE -> fp16 outputs (q pre-scaled) ========
__global__ void __launch_bounds__(256) rmsnorm_rope(
    const float* __restrict__ gq, const float* __restrict__ gk,
    const float* __restrict__ freqs, const int* __restrict__ gsz)
{
    const int t = blockIdx.x;
    const int which = blockIdx.y;
    const float* row = (which ? g_k : g_q) + (size_t)t * DIM;
    __half* rowo = (which ? g_kt : g_qt) + (size_t)t * DIM;
    const float oscale = which ? 1.0f : (SCALE * LOG2E);
    const float* g = which ? gk : gq;
    const int tid = threadIdx.x;

    float ss = 0.f;
    for (int i = tid; i < DIM; i += 256) {
        float v = row[i];
        ss += v * v;
    }
    __shared__ float red[8];
#pragma unroll
    for (int o = 16; o; o >>= 1) ss += __shfl_xor_sync(0xffffffffu, ss, o);
    if ((tid & 31) == 0) red[tid >> 5] = ss;
    __syncthreads();
    if (tid < 8) {
        float v = red[tid];
#pragma unroll
        for (int o = 4; o; o >>= 1) v += __shfl_xor_sync(0xffu, v, o);
        if (tid == 0) red[0] = v;
    }
    __syncthreads();
    const float rms = rsqrtf(red[0] * (1.0f / DIM) + EPS);

    const int Hs = gsz[1], Ws = gsz[2];
    const int fi = t / (Hs * Ws);
    const int hi = (t / Ws) % Hs;
    const int wi = t % Ws;

    for (int p = tid; p < HEADS * 64; p += 256) {
        const int h = p >> 6;
        const int j = p & 63;
        const int pos = (j < 22) ? fi : ((j < 43) ? hi : wi);
        const float ang = freqs[pos * 64 + j];
        float c, s;
        sincosf(ang, &s, &c);
        const int d0 = h * HD + 2 * j;
        const float x0 = row[d0]     * rms * g[d0];
        const float x1 = row[d0 + 1] * rms * g[d0 + 1];
        __half2 o = __floats2half2_rn((x0 * c - x1 * s) * oscale,
                                      (x0 * s + x1 * c) * oscale);
        *(__half2*)(rowo + d0) = o;
    }
}

// ====== flash attention (fp16 mma, register-resident fp32 softmax) ======
#define FQ 64
#define FK 64
#define QST_H 136     // 272B rows; conflict-free ldsm
#define KST_H 136
#define VST_H 136
#define SST_H 72      // 144B rows (P tile)
#define FLASH_SMEM_BYTES (FQ*QST_H*2 + FK*KST_H*2 + FQ*SST_H*2 + 2*FQ*4 + 2*FQ*4*4)

__global__ void __launch_bounds__(256, 2) flash_f16()
{
    extern __shared__ __align__(16) char smc[];
    __half* Qs  = (__half*)smc;
    __half* KVs = Qs + FQ * QST_H;
    __half* Ss  = KVs + FK * KST_H;
    float* m_s = (float*)(Ss + FQ * SST_H);
    float* l_s = m_s + FQ;
    float* pm  = l_s + FQ;          // [64][4] warp-partial max
    float* ps  = pm + FQ * 4;       // [64][4] warp-partial sum

    const int tid = threadIdx.x;
    const int lane = tid & 31;
    const int wid = tid >> 5;
    const int wm = wid >> 2;
    const int wn = wid & 3;
    const int h  = blockIdx.y;
    const int q0 = blockIdx.x * FQ;

    const int tr = lane & 7;
    const int mq = lane >> 3;
    const int a_row = tr + 8 * (mq & 1);
    const int a_kb  = 16 * (mq >> 1);
    const int b_row = tr + 8 * (mq >> 1);
    const int b_kb  = 16 * (mq & 1);
    const int v_krow = tr + 8 * (mq & 1);
    const int v_noff = 8 * (mq >> 1);

    const uint32_t Qa = smem_addr(Qs);
    const uint32_t Ka = smem_addr(KVs);
    const uint32_t Sa = smem_addr(Ss);

    int srow[4], scol[4];
#pragma unroll
    for (int j = 0; j < 4; ++j) {
        int i = tid + j * 256;
        srow[j] = i >> 4;
        scol[j] = (i & 15) * 8;
    }

    // Q tile (pre-scaled fp16)
#pragma unroll
    for (int j = 0; j < 4; ++j) {
        uint4 v = *(const uint4*)(g_qt + (size_t)(q0 + srow[j]) * DIM + h * HD + scol[j]);
        *(uint4*)&Qs[srow[j] * QST_H + scol[j]] = v;
    }
    if (tid < FQ) { m_s[tid] = -3.0e38f; l_s[tid] = 0.f; }

    float O[8][4];
#pragma unroll
    for (int t = 0; t < 8; ++t) O[t][0] = O[t][1] = O[t][2] = O[t][3] = 0.f;

    uint4 kreg[4];
#pragma unroll
    for (int j = 0; j < 4; ++j)
        kreg[j] = *(const uint4*)(g_kt + (size_t)srow[j] * DIM + h * HD + scol[j]);

    for (int t0 = 0; t0 < LTOK; t0 += FK) {
        __syncthreads();   // (1) prev PV reads of KVs/Ss done
#pragma unroll
        for (int j = 0; j < 4; ++j)
            *(uint4*)&KVs[srow[j] * KST_H + scol[j]] = kreg[j];
        __syncthreads();   // (2) K visible

        uint4 vreg[4];
#pragma unroll
        for (int j = 0; j < 4; ++j)
            vreg[j] = *(const uint4*)(g_vt + (size_t)(t0 + srow[j]) * DIM + h * HD + scol[j]);

        // S = Q K^T (log2-domain, fp32 accum): warp tile 32(q) x 16(kv)
        float Sacc[2][2][4] = {};
#pragma unroll
        for (int ks = 0; ks < 8; ++ks) {
            const int kbb = ks * 32;
            uint32_t af[2][4], bf[2][2];
#pragma unroll
            for (int mt = 0; mt < 2; ++mt) {
                uint32_t addr = Qa + (wm * 32 + mt * 16 + a_row) * (QST_H * 2) + kbb + a_kb;
                ldsm_x4(af[mt][0], af[mt][1], af[mt][2], af[mt][3], addr);
            }
            {
                uint32_t addr = Ka + (wn * 16 + b_row) * (KST_H * 2) + kbb + b_kb;
                ldsm_x4(bf[0][0], bf[0][1], bf[1][0], bf[1][1], addr);
            }
#pragma unroll
            for (int mt = 0; mt < 2; ++mt)
#pragma unroll
                for (int nt = 0; nt < 2; ++nt)
                    mma_f16(Sacc[mt][nt],
                            af[mt][0], af[mt][1], af[mt][2], af[mt][3],
                            bf[nt][0], bf[nt][1]);
        }

        // warp-partial row max over this warp's 16 cols
        float pmax[2][2];
#pragma unroll
        for (int mt = 0; mt < 2; ++mt) {
            pmax[mt][0] = fmaxf(fmaxf(Sacc[mt][0][0], Sacc[mt][0][1]),
                                fmaxf(Sacc[mt][1][0], Sacc[mt][1][1]));
            pmax[mt][1] = fmaxf(fmaxf(Sacc[mt][0][2], Sacc[mt][0][3]),
                                fmaxf(Sacc[mt][1][2], Sacc[mt][1][3]));
#pragma unroll
            for (int rs = 0; rs < 2; ++rs) {
                pmax[mt][rs] = fmaxf(pmax[mt][rs], __shfl_xor_sync(0xffffffffu, pmax[mt][rs], 1));
                pmax[mt][rs] = fmaxf(pmax[mt][rs], __shfl_xor_sync(0xffffffffu, pmax[mt][rs], 2));
            }
        }
        if ((lane & 3) == 0) {
#pragma unroll
            for (int mt = 0; mt < 2; ++mt)
#pragma unroll
                for (int rs = 0; rs < 2; ++rs) {
                    int row = wm * 32 + mt * 16 + (lane >> 2) + rs * 8;
                    pm[row * 4 + wn] = pmax[mt][rs];
                }
        }

        // prefetch K(t+1)
        if (t0 + FK < LTOK) {
#pragma unroll
            for (int j = 0; j < 4; ++j)
                kreg[j] = *(const uint4*)(g_kt + (size_t)(t0 + FK + srow[j]) * DIM + h * HD + scol[j]);
        }
        __syncthreads();   // (3) pm visible; KVs free (S-phase done)

        // V -> smem
#pragma unroll
        for (int j = 0; j < 4; ++j)
            *(uint4*)&KVs[srow[j] * VST_H + scol[j]] = vreg[j];

        // per-thread: mnew, f; P = exp2(S - mnew); partial sums
        float mnew[2][2], fsc[2][2], psum[2][2];
#pragma unroll
        for (int mt = 0; mt < 2; ++mt)
#pragma unroll
            for (int rs = 0; rs < 2; ++rs) {
                int row = wm * 32 + mt * 16 + (lane >> 2) + rs * 8;
                float4 pv = *(float4*)&pm[row * 4];
                float mold = m_s[row];
                float mx = fmaxf(fmaxf(pv.x, pv.y), fmaxf(pv.z, pv.w));
                float mn = fmaxf(mold, mx);
                mnew[mt][rs] = mn;
                fsc[mt][rs] = exp2f(mold - mn);
                psum[mt][rs] = 0.f;
            }
#pragma unroll
        for (int mt = 0; mt < 2; ++mt) {
            int r = wm * 32 + mt * 16 + (lane >> 2);
            int c = wn * 16 + (lane & 3) * 2;
#pragma unroll
            for (int nt = 0; nt < 2; ++nt) {
                float p00 = exp2f(Sacc[mt][nt][0] - mnew[mt][0]);
                float p01 = exp2f(Sacc[mt][nt][1] - mnew[mt][0]);
                float p10 = exp2f(Sacc[mt][nt][2] - mnew[mt][1]);
                float p11 = exp2f(Sacc[mt][nt][3] - mnew[mt][1]);
                psum[mt][0] += p00 + p01;
                psum[mt][1] += p10 + p11;
                *(__half2*)&Ss[r * SST_H + c + nt * 8] = __floats2half2_rn(p00, p01);
                *(__half2*)&Ss[(r + 8) * SST_H + c + nt * 8] = __floats2half2_rn(p10, p11);
            }
        }
#pragma unroll
        for (int mt = 0; mt < 2; ++mt)
#pragma unroll
            for (int rs = 0; rs < 2; ++rs) {
                psum[mt][rs] += __shfl_xor_sync(0xffffffffu, psum[mt][rs], 1);
                psum[mt][rs] += __shfl_xor_sync(0xffffffffu, psum[mt][rs], 2);
            }
        if ((lane & 3) == 0) {
#pragma unroll
            for (int mt = 0; mt < 2; ++mt)
#pragma unroll
                for (int rs = 0; rs < 2; ++rs) {
                    int row = wm * 32 + mt * 16 + (lane >> 2) + rs * 8;
                    ps[row * 4 + wn] = psum[mt][rs];
                }
        }

        // O rescale (uses f from pre-update mold)
#pragma unroll
        for (int mt = 0; mt < 2; ++mt) {
            float f0 = fsc[mt][0], f1 = fsc[mt][1];
#pragma unroll
            for (int nt = 0; nt < 4; ++nt) {
                O[mt * 4 + nt][0] *= f0; O[mt * 4 + nt][1] *= f0;
                O[mt * 4 + nt][2] *= f1; O[mt * 4 + nt][3] *= f1;
            }
        }
        __syncthreads();   // (4) P + ps + V visible; all mold reads done

        // designated m/l update (one thread per row)
        if (wn == 0 && (lane & 3) == 0) {
#pragma unroll
            for (int mt = 0; mt < 2; ++mt)
#pragma unroll
                for (int rs = 0; rs < 2; ++rs) {
                    int row = wm * 32 + mt * 16 + (lane >> 2) + rs * 8;
                    float4 s4 = *(float4*)&ps[row * 4];
                    l_s[row] = l_s[row] * fsc[mt][rs] + (s4.x + s4.y + s4.z + s4.w);
                    m_s[row] = mnew[mt][rs];
                }
        }

        // O += P @ V : warp tile 32(q) x 32(hd)
        const uint32_t Va = Ka;
#pragma unroll
        for (int ks = 0; ks < 4; ++ks) {
            const int kb = ks * 16;
            uint32_t af[2][4], bf[4][2];
#pragma unroll
            for (int mt = 0; mt < 2; ++mt) {
                uint32_t addr = Sa + (wm * 32 + mt * 16 + a_row) * (SST_H * 2) + ks * 32 + a_kb;
                ldsm_x4(af[mt][0], af[mt][1], af[mt][2], af[mt][3], addr);
            }
#pragma unroll
            for (int p = 0; p < 2; ++p) {
                int c0 = wn * 32 + p * 16;
                uint32_t addr = Va + (kb + v_krow) * (VST_H * 2) + (c0 + v_noff) * 2;
                ldsm_x4_t(bf[2*p][0], bf[2*p][1], bf[2*p+1][0], bf[2*p+1][1], addr);
            }
#pragma unroll
            for (int mt = 0; mt < 2; ++mt)
#pragma unroll
                for (int nt = 0; nt < 4; ++nt)
                    mma_f16(O[mt * 4 + nt],
                            af[mt][0], af[mt][1], af[mt][2], af[mt][3],
                            bf[nt][0], bf[nt][1]);
        }
    }

    __syncthreads();   // last l_s/m_s updates visible

    // finalize -> fp16 g_ot
#pragma unroll
    for (int mt = 0; mt < 2; ++mt) {
        int r = wm * 32 + mt * 16 + (lane >> 2);
        float inv0 = 1.f / l_s[r], inv1 = 1.f / l_s[r + 8];
#pragma unroll
        for (int nt = 0; nt < 4; ++nt) {
            int c = wn * 32 + nt * 8 + (lane & 3) * 2;
            float* a4 = O[mt * 4 + nt];
            *(__half2*)(g_ot + (size_t)(q0 + r) * DIM + h * HD + c) =
                __floats2half2_rn(a4[0] * inv0, a4[1] * inv0);
            *(__half2*)(g_ot + (size_t)(q0 + r + 8) * DIM + h * HD + c) =
                __floats2half2_rn(a4[2] * inv1, a4[3] * inv1);
        }
    }
}

// ================= launch =================
extern "C" void kernel_launch(void* const* d_in, const int* in_sizes, int n_in,
                              void* d_out, int out_size)
{
    const float* x          = (const float*)d_in[0];
    const int*   grid_sizes = (const int*)d_in[2];
    const float* freqs      = (const float*)d_in[3];
    const float* Wq = (const float*)d_in[4];
    const float* bq = (const float*)d_in[5];
    const float* Wk = (const float*)d_in[6];
    const float* bk = (const float*)d_in[7];
    const float* Wv = (const float*)d_in[8];
    const float* bv = (const float*)d_in[9];
    const float* Wo = (const float*)d_in[10];
    const float* bo = (const float*)d_in[11];
    const float* gq = (const float*)d_in[12];
    const float* gk = (const float*)d_in[13];
    float* out = (float*)d_out;

    __half *xt, *wt, *vt;
    float* vp;
    cudaGetSymbolAddress((void**)&xt, g_xt);
    cudaGetSymbolAddress((void**)&wt, g_wt);
    cudaGetSymbolAddress((void**)&vt, g_vt);
    cudaGetSymbolAddress((void**)&vp, g_v);

    cudaFuncSetAttribute(flash_f16, cudaFuncAttributeMaxDynamicSharedMemorySize, FLASH_SMEM_BYTES);
    cudaFuncSetAttribute(qkv_gemm_f16, cudaFuncAttributeMaxDynamicSharedMemorySize, GM_SMEM_BYTES);
    cudaFuncSetAttribute(out_gemm_f16, cudaFuncAttributeMaxDynamicSharedMemorySize, GM_SMEM_BYTES);

    const int NX4 = LTOK * DIM / 4;
    const int NW4 = DIM * DIM / 4;

    convert_f16<<<(NX4 + 255) / 256, 256>>>((const float4*)x,  (uint2*)xt, NX4);
    convert_f16<<<(NW4 + 255) / 256, 256>>>((const float4*)Wq, (uint2*)(wt + 0 * (size_t)DIM * DIM), NW4);
    convert_f16<<<(NW4 + 255) / 256, 256>>>((const float4*)Wk, (uint2*)(wt + 1 * (size_t)DIM * DIM), NW4);
    convert_f16<<<(NW4 + 255) / 256, 256>>>((const float4*)Wv, (uint2*)(wt + 2 * (size_t)DIM * DIM), NW4);
    convert_f16<<<(NW4 + 255) / 256, 256>>>((const float4*)Wo, (uint2*)(wt + 3 * (size_t)DIM * DIM), NW4);

    dim3 gqkv(DIM / GM_BN, (LTOK + GM_BM - 1) / GM_BM, 3);   // 12 x 28 x 3
    dim3 gout(DIM / GM_BN, (LTOK + GM_BM - 1) / GM_BM);      // 12 x 28

    qkv_gemm_f16<<<gqkv, 256, GM_SMEM_BYTES>>>(bq, bk, bv);
    rmsnorm_rope<<<dim3(LTOK, 2), 256>>>(gq, gk, freqs, grid_sizes);
    convert_f16<<<(NX4 + 255) / 256, 256>>>((const float4*)vp, (uint2*)vt, NX4);
    flash_f16<<<dim3(LTOK / FQ, HEADS), 256, FLASH_SMEM_BYTES>>>();
    out_gemm_f16<<<gout, 256, GM_SMEM_BYTES>>>(bo, out);
}

// round 14
// speedup vs baseline: 2.0538x; 1.0574x over previous
#include <cuda_runtime.h>
#include <cuda_fp16.h>
#include <cstdint>

#define DIM    1536
#define HEADS  12
#define HD     128
#define LTOK   3520
#define EPS    1e-6f
#define SCALE  0.08838834764831845f   // 1/sqrt(128)
#define LOG2E  1.4426950408889634f

// ---------------- scratch (no allocation allowed) ----------------
__device__ float  g_q[LTOK * DIM];    // q fp32; later reused as out-partial 0
__device__ float  g_k[LTOK * DIM];    // k fp32; later reused as out-partial 1
__device__ __half g_xt[LTOK * DIM];
__device__ __half g_wt[4][DIM * DIM];
__device__ __half g_qt[LTOK * DIM];   // rmsnorm+rope q, *SCALE*log2e
__device__ __half g_kt[LTOK * DIM];   // rmsnorm+rope k
__device__ __half g_vt[LTOK * DIM];   // v (written by qkv gemm epilogue)
__device__ __half g_ot[LTOK * DIM];   // attention output

// ---------------- helpers ----------------
__device__ __forceinline__ void mma_f16(float c[4],
    uint32_t a0, uint32_t a1, uint32_t a2, uint32_t a3,
    uint32_t b0, uint32_t b1)
{
    asm volatile(
        "mma.sync.aligned.m16n8k16.row.col.f32.f16.f16.f32 "
        "{%0,%1,%2,%3}, {%4,%5,%6,%7}, {%8,%9}, {%0,%1,%2,%3};\n"
        : "+f"(c[0]), "+f"(c[1]), "+f"(c[2]), "+f"(c[3])
        : "r"(a0), "r"(a1), "r"(a2), "r"(a3), "r"(b0), "r"(b1));
}
__device__ __forceinline__ void ldsm_x4(uint32_t& r0, uint32_t& r1,
                                        uint32_t& r2, uint32_t& r3, uint32_t addr)
{
    asm volatile("ldmatrix.sync.aligned.m8n8.x4.shared.b16 {%0,%1,%2,%3}, [%4];"
                 : "=r"(r0), "=r"(r1), "=r"(r2), "=r"(r3) : "r"(addr));
}
__device__ __forceinline__ void ldsm_x4_t(uint32_t& r0, uint32_t& r1,
                                          uint32_t& r2, uint32_t& r3, uint32_t addr)
{
    asm volatile("ldmatrix.sync.aligned.m8n8.x4.trans.shared.b16 {%0,%1,%2,%3}, [%4];"
                 : "=r"(r0), "=r"(r1), "=r"(r2), "=r"(r3) : "r"(addr));
}
__device__ __forceinline__ uint32_t smem_addr(const void* p) {
    return (uint32_t)__cvta_generic_to_shared(p);
}
__device__ __forceinline__ void cp_async16(uint32_t dst, const void* src) {
    asm volatile("cp.async.cg.shared.global [%0], [%1], 16;" :: "r"(dst), "l"(src));
}
#define CP_COMMIT() asm volatile("cp.async.commit_group;" ::: "memory")
#define CP_WAIT1()  asm volatile("cp.async.wait_group 1;" ::: "memory")

// ================= fp16 convert kernel (gmem -> gmem) =================
__global__ void __launch_bounds__(256) convert_f16(const float4* __restrict__ src,
                                                   uint2* __restrict__ dst, int n4)
{
    int i = blockIdx.x * blockDim.x + threadIdx.x;
    if (i < n4) {
        float4 v = src[i];
        __half2 lo = __floats2half2_rn(v.x, v.y);
        __half2 hi = __floats2half2_rn(v.z, v.w);
        dst[i] = make_uint2(*(uint32_t*)&lo, *(uint32_t*)&hi);
    }
}

// ============ reduce: out = p0 + p1 + bias =============================
__global__ void __launch_bounds__(256) reduce_bias(
    const float4* __restrict__ p0, const float4* __restrict__ p1,
    const float4* __restrict__ bias, float4* __restrict__ out, int n4)
{
    int i = blockIdx.x * blockDim.x + threadIdx.x;
    if (i < n4) {
        float4 a = p0[i], b = p1[i], bb = bias[i % (DIM / 4)];
        out[i] = make_float4(a.x + b.x + bb.x, a.y + b.y + bb.y,
                             a.z + b.z + bb.z, a.w + b.w + bb.w);
    }
}

// ================= fp16 GEMM core: C = A[:,k0:k0+klen] @ B^T (+bias) ====
// BM=BN=128, BK=64 halves, 256 threads (8 warps 2x4), warp tile 64x32.
#define GM_BM 128
#define GM_BN 128
#define GM_BK 64
#define GSTR_H 72
#define GM_TILE_H (GM_BM * GSTR_H)
#define GM_STAGE_H (2 * GM_TILE_H)
#define GM_SMEM_BYTES (3 * GM_STAGE_H * 2)   // 110592

// out mode: bias!=null -> add bias. Ch!=null -> write fp16 to Ch, else fp32 Cf.
__device__ __forceinline__ void gemm_tile_f16(
    const __half* __restrict__ A, const __half* __restrict__ B,
    const float* __restrict__ bias, float* __restrict__ Cf, __half* __restrict__ Ch,
    int M, int N, int K, int kbeg, int klen, int m0, int n0, __half* sm)
{
    const int tid = threadIdx.x;
    const int lane = tid & 31;
    const int wid = tid >> 5;
    const int wm = wid >> 2;
    const int wn = wid & 3;

    const int tr = lane & 7;
    const int mq = lane >> 3;
    const int a_row = tr + 8 * (mq & 1);
    const int a_kb  = 16 * (mq >> 1);
    const int b_row = tr + 8 * (mq >> 1);
    const int b_kb  = 16 * (mq & 1);

    int r2[4], kc2[4], arow[4], brow[4];
#pragma unroll
    for (int i = 0; i < 4; ++i) {
        int s = tid + i * 256;
        r2[i] = s >> 3;
        kc2[i] = (s & 7) * 8;
        arow[i] = min(m0 + r2[i], M - 1);
        brow[i] = n0 + r2[i];
    }

    const uint32_t smu = smem_addr(sm);

    auto fill = [&](int st, int k0) {
        const uint32_t base = smu + 2u * (st * GM_STAGE_H);
#pragma unroll
        for (int i = 0; i < 4; ++i)
            cp_async16(base + 2u * (r2[i] * GSTR_H + kc2[i]),
                       A + (size_t)arow[i] * K + k0 + kc2[i]);
#pragma unroll
        for (int i = 0; i < 4; ++i)
            cp_async16(base + 2u * (GM_TILE_H + r2[i] * GSTR_H + kc2[i]),
                       B + (size_t)brow[i] * K + k0 + kc2[i]);
        CP_COMMIT();
    };

    fill(0, kbeg);
    fill(1, kbeg + GM_BK);

    float acc[16][4];
#pragma unroll
    for (int t = 0; t < 16; ++t)
        acc[t][0] = acc[t][1] = acc[t][2] = acc[t][3] = 0.f;

    const int NIT = klen / GM_BK;
    int st = 0;
    for (int it = 0; it < NIT; ++it) {
        CP_WAIT1();
        __syncthreads();
        if (it + 2 < NIT) fill((st + 2) % 3, kbeg + (it + 2) * GM_BK);
        else CP_COMMIT();

        const uint32_t Ab = smu + 2u * (st * GM_STAGE_H);
        const uint32_t Bb = Ab + 2u * GM_TILE_H;
#pragma unroll
        for (int ks = 0; ks < 4; ++ks) {
            const int kbb = ks * 32;
            uint32_t af[4][4], bf[4][2];
#pragma unroll
            for (int mt = 0; mt < 4; ++mt) {
                uint32_t addr = Ab + (wm * 64 + mt * 16 + a_row) * (GSTR_H * 2) + kbb + a_kb;
                ldsm_x4(af[mt][0], af[mt][1], af[mt][2], af[mt][3], addr);
            }
#pragma unroll
            for (int p = 0; p < 2; ++p) {
                uint32_t addr = Bb + (wn * 32 + p * 16 + b_row) * (GSTR_H * 2) + kbb + b_kb;
                ldsm_x4(bf[2*p][0], bf[2*p][1], bf[2*p+1][0], bf[2*p+1][1], addr);
            }
#pragma unroll
            for (int mt = 0; mt < 4; ++mt)
#pragma unroll
                for (int nt = 0; nt < 4; ++nt)
                    mma_f16(acc[mt * 4 + nt],
                            af[mt][0], af[mt][1], af[mt][2], af[mt][3],
                            bf[nt][0], bf[nt][1]);
        }
        st = (st + 1) % 3;
    }

    // epilogue
#pragma unroll
    for (int nt = 0; nt < 4; ++nt) {
        int c = n0 + wn * 32 + nt * 8 + (lane & 3) * 2;
        float b0 = 0.f, b1 = 0.f;
        if (bias) { b0 = bias[c]; b1 = bias[c + 1]; }
#pragma unroll
        for (int mt = 0; mt < 4; ++mt) {
            int r = m0 + wm * 64 + mt * 16 + (lane >> 2);
            float* a4 = acc[mt * 4 + nt];
            if (Ch) {
                if (r < M)
                    *(__half2*)(Ch + (size_t)r * N + c) = __floats2half2_rn(a4[0] + b0, a4[1] + b1);
                if (r + 8 < M)
                    *(__half2*)(Ch + (size_t)(r + 8) * N + c) = __floats2half2_rn(a4[2] + b0, a4[3] + b1);
            } else {
                if (r < M)
                    *(float2*)(Cf + (size_t)r * N + c) = make_float2(a4[0] + b0, a4[1] + b1);
                if (r + 8 < M)
                    *(float2*)(Cf + (size_t)(r + 8) * N + c) = make_float2(a4[2] + b0, a4[3] + b1);
            }
        }
    }
}

__global__ void __launch_bounds__(256, 2) qkv_gemm_f16(
    const float* __restrict__ bq, const float* __restrict__ bk,
    const float* __restrict__ bv)
{
    extern __shared__ __align__(16) __half smh[];
    const float* b; float* outF = nullptr; __half* outH = nullptr;
    if (blockIdx.z == 0)      { b = bq; outF = g_q; }
    else if (blockIdx.z == 1) { b = bk; outF = g_k; }
    else                      { b = bv; outH = g_vt; }
    gemm_tile_f16(g_xt, g_wt[blockIdx.z], b, outF, outH, LTOK, DIM, DIM,
                  0, DIM, blockIdx.y * GM_BM, blockIdx.x * GM_BN, smh);
}

// split-K out projection: z=0 -> partial in g_q (K 0..768), z=1 -> g_k (768..1536)
__global__ void __launch_bounds__(256, 2) out_gemm_f16()
{
    extern __shared__ __align__(16) __half smh[];
    float* part = blockIdx.z ? g_k : g_q;
    gemm_tile_f16(g_ot, g_wt[3], nullptr, part, nullptr, LTOK, DIM, DIM,
                  blockIdx.z * (DIM / 2), DIM / 2,
                  blockIdx.y * GM_BM, blockIdx.x * GM_BN, smh);
}

// ============ fused RMSNorm + RoPE -> fp16 outputs (q pre-scaled) ========
__global__ void __launch_bounds__(256) rmsnorm_rope(
    const float* __restrict__ gq, const float* __restrict__ gk,
    const float* __restrict__ freqs, const int* __restrict__ gsz)
{
    const int t = blockIdx.x;
    const int which = blockIdx.y;
    const float* row = (which ? g_k : g_q) + (size_t)t * DIM;
    __half* rowo = (which ? g_kt : g_qt) + (size_t)t * DIM;
    const float oscale = which ? 1.0f : (SCALE * LOG2E);
    const float* g = which ? gk : gq;
    const int tid = threadIdx.x;

    float ss = 0.f;
    for (int i = tid; i < DIM; i += 256) {
        float v = row[i];
        ss += v * v;
    }
    __shared__ float red[8];
#pragma unroll
    for (int o = 16; o; o >>= 1) ss += __shfl_xor_sync(0xffffffffu, ss, o);
    if ((tid & 31) == 0) red[tid >> 5] = ss;
    __syncthreads();
    if (tid < 8) {
        float v = red[tid];
#pragma unroll
        for (int o = 4; o; o >>= 1) v += __shfl_xor_sync(0xffu, v, o);
        if (tid == 0) red[0] = v;
    }
    __syncthreads();
    const float rms = rsqrtf(red[0] * (1.0f / DIM) + EPS);

    const int Hs = gsz[1], Ws = gsz[2];
    const int fi = t / (Hs * Ws);
    const int hi = (t / Ws) % Hs;
    const int wi = t % Ws;

    for (int p = tid; p < HEADS * 64; p += 256) {
        const int h = p >> 6;
        const int j = p & 63;
        const int pos = (j < 22) ? fi : ((j < 43) ? hi : wi);
        const float ang = freqs[pos * 64 + j];
        float c, s;
        sincosf(ang, &s, &c);
        const int d0 = h * HD + 2 * j;
        const float x0 = row[d0]     * rms * g[d0];
        const float x1 = row[d0 + 1] * rms * g[d0 + 1];
        __half2 o = __floats2half2_rn((x0 * c - x1 * s) * oscale,
                                      (x0 * s + x1 * c) * oscale);
        *(__half2*)(rowo + d0) = o;
    }
}

// ====== flash attention: fp16 mma, K double-buffer + V buffer, 2 bars/iter
#define FQ 64
#define FK 64
#define TST_H 136     // tile row stride (272B rows; conflict-free ldsm)
#define SST_H 72      // P tile rows (144B)
#define FLASH_SMEM_BYTES (4*FQ*TST_H*2 + FQ*SST_H*2 + (2*FQ + 8*FQ)*4)

__global__ void __launch_bounds__(256, 2) flash_f16()
{
    extern __shared__ __align__(16) char smc[];
    __half* Qs = (__half*)smc;
    __half* K0 = Qs + FQ * TST_H;
    __half* K1 = K0 + FQ * TST_H;
    __half* Vs = K1 + FQ * TST_H;
    __half* Ss = Vs + FQ * TST_H;
    float* m_s = (float*)(Ss + FQ * SST_H);
    float* l_s = m_s + FQ;
    float* pm  = l_s + FQ;          // [64][4]
    float* ps  = pm + FQ * 4;       // [64][4]

    const int tid = threadIdx.x;
    const int lane = tid & 31;
    const int wid = tid >> 5;
    const int wm = wid >> 2;
    const int wn = wid & 3;
    const int h  = blockIdx.y;
    const int q0 = blockIdx.x * FQ;

    const int tr = lane & 7;
    const int mq = lane >> 3;
    const int a_row = tr + 8 * (mq & 1);
    const int a_kb  = 16 * (mq >> 1);
    const int b_row = tr + 8 * (mq >> 1);
    const int b_kb  = 16 * (mq & 1);
    const int v_krow = tr + 8 * (mq & 1);
    const int v_noff = 8 * (mq >> 1);

    const uint32_t Qa = smem_addr(Qs);
    const uint32_t K0a = smem_addr(K0);
    const uint32_t K1a = smem_addr(K1);
    const uint32_t Va = smem_addr(Vs);
    const uint32_t Sa = smem_addr(Ss);

    int srow[4], scol[4];
#pragma unroll
    for (int j = 0; j < 4; ++j) {
        int i = tid + j * 256;
        srow[j] = i >> 4;
        scol[j] = (i & 15) * 8;
    }

    // Q tile + K(0)
#pragma unroll
    for (int j = 0; j < 4; ++j) {
        uint4 v = *(const uint4*)(g_qt + (size_t)(q0 + srow[j]) * DIM + h * HD + scol[j]);
        *(uint4*)&Qs[srow[j] * TST_H + scol[j]] = v;
        uint4 kv = *(const uint4*)(g_kt + (size_t)srow[j] * DIM + h * HD + scol[j]);
        *(uint4*)&K0[srow[j] * TST_H + scol[j]] = kv;
    }
    if (tid < FQ) { m_s[tid] = -3.0e38f; l_s[tid] = 0.f; }

    float O[8][4];
#pragma unroll
    for (int t = 0; t < 8; ++t) O[t][0] = O[t][1] = O[t][2] = O[t][3] = 0.f;

    __syncthreads();   // Q, K0, m/l visible

    int it = 0;
    for (int t0 = 0; t0 < LTOK; t0 += FK, ++it) {
        const uint32_t Kcur = (it & 1) ? K1a : K0a;
        __half* Knext = (it & 1) ? K0 : K1;

        // early loads: V(t) and K(t+1)
        uint4 vreg[4], kreg[4];
#pragma unroll
        for (int j = 0; j < 4; ++j)
            vreg[j] = *(const uint4*)(g_vt + (size_t)(t0 + srow[j]) * DIM + h * HD + scol[j]);
        const bool has_next = (t0 + FK < LTOK);
        if (has_next) {
#pragma unroll
            for (int j = 0; j < 4; ++j)
                kreg[j] = *(const uint4*)(g_kt + (size_t)(t0 + FK + srow[j]) * DIM + h * HD + scol[j]);
        }

        // S = Q K^T (log2-domain, fp32 accum): warp tile 32(q) x 16(kv)
        float Sacc[2][2][4] = {};
#pragma unroll
        for (int ks = 0; ks < 8; ++ks) {
            const int kbb = ks * 32;
            uint32_t af[2][4], bf[2][2];
#pragma unroll
            for (int mt = 0; mt < 2; ++mt) {
                uint32_t addr = Qa + (wm * 32 + mt * 16 + a_row) * (TST_H * 2) + kbb + a_kb;
                ldsm_x4(af[mt][0], af[mt][1], af[mt][2], af[mt][3], addr);
            }
            {
                uint32_t addr = Kcur + (wn * 16 + b_row) * (TST_H * 2) + kbb + b_kb;
                ldsm_x4(bf[0][0], bf[0][1], bf[1][0], bf[1][1], addr);
            }
#pragma unroll
            for (int mt = 0; mt < 2; ++mt)
#pragma unroll
                for (int nt = 0; nt < 2; ++nt)
                    mma_f16(Sacc[mt][nt],
                            af[mt][0], af[mt][1], af[mt][2], af[mt][3],
                            bf[nt][0], bf[nt][1]);
        }

        // warp-partial row max
        float pmax[2][2];
#pragma unroll
        for (int mt = 0; mt < 2; ++mt) {
            pmax[mt][0] = fmaxf(fmaxf(Sacc[mt][0][0], Sacc[mt][0][1]),
                                fmaxf(Sacc[mt][1][0], Sacc[mt][1][1]));
            pmax[mt][1] = fmaxf(fmaxf(Sacc[mt][0][2], Sacc[mt][0][3]),
                                fmaxf(Sacc[mt][1][2], Sacc[mt][1][3]));
#pragma unroll
            for (int rs = 0; rs < 2; ++rs) {
                pmax[mt][rs] = fmaxf(pmax[mt][rs], __shfl_xor_sync(0xffffffffu, pmax[mt][rs], 1));
                pmax[mt][rs] = fmaxf(pmax[mt][rs], __shfl_xor_sync(0xffffffffu, pmax[mt][rs], 2));
            }
        }
        if ((lane & 3) == 0) {
#pragma unroll
            for (int mt = 0; mt < 2; ++mt)
#pragma unroll
                for (int rs = 0; rs < 2; ++rs) {
                    int row = wm * 32 + mt * 16 + (lane >> 2) + rs * 8;
                    pm[row * 4 + wn] = pmax[mt][rs];
                }
        }
        __syncthreads();   // A: pm visible; V buffer + K-next buffer free

        // commit V(t) and K(t+1)
#pragma unroll
        for (int j = 0; j < 4; ++j)
            *(uint4*)&Vs[srow[j] * TST_H + scol[j]] = vreg[j];
        if (has_next) {
#pragma unroll
            for (int j = 0; j < 4; ++j)
                *(uint4*)&Knext[srow[j] * TST_H + scol[j]] = kreg[j];
        }

        // softmax: mnew, f, P, partial sums
        float mnew[2][2], fsc[2][2], psum[2][2];
#pragma unroll
        for (int mt = 0; mt < 2; ++mt)
#pragma unroll
            for (int rs = 0; rs < 2; ++rs) {
                int row = wm * 32 + mt * 16 + (lane >> 2) + rs * 8;
                float4 pv = *(float4*)&pm[row * 4];
                float mold = m_s[row];
                float mx = fmaxf(fmaxf(pv.x, pv.y), fmaxf(pv.z, pv.w));
                float mn = fmaxf(mold, mx);
                mnew[mt][rs] = mn;
                fsc[mt][rs] = exp2f(mold - mn);
                psum[mt][rs] = 0.f;
            }
#pragma unroll
        for (int mt = 0; mt < 2; ++mt) {
            int r = wm * 32 + mt * 16 + (lane >> 2);
            int c = wn * 16 + (lane & 3) * 2;
#pragma unroll
            for (int nt = 0; nt < 2; ++nt) {
                float p00 = exp2f(Sacc[mt][nt][0] - mnew[mt][0]);
                float p01 = exp2f(Sacc[mt][nt][1] - mnew[mt][0]);
                float p10 = exp2f(Sacc[mt][nt][2] - mnew[mt][1]);
                float p11 = exp2f(Sacc[mt][nt][3] - mnew[mt][1]);
                psum[mt][0] += p00 + p01;
                psum[mt][1] += p10 + p11;
                *(__half2*)&Ss[r * SST_H + c + nt * 8] = __floats2half2_rn(p00, p01);
                *(__half2*)&Ss[(r + 8) * SST_H + c + nt * 8] = __floats2half2_rn(p10, p11);
            }
        }
#pragma unroll
        for (int mt = 0; mt < 2; ++mt)
#pragma unroll
            for (int rs = 0; rs < 2; ++rs) {
                psum[mt][rs] += __shfl_xor_sync(0xffffffffu, psum[mt][rs], 1);
                psum[mt][rs] += __shfl_xor_sync(0xffffffffu, psum[mt][rs], 2);
            }
        if ((lane & 3) == 0) {
#pragma unroll
            for (int mt = 0; mt < 2; ++mt)
#pragma unroll
                for (int rs = 0; rs < 2; ++rs) {
                    int row = wm * 32 + mt * 16 + (lane >> 2) + rs * 8;
                    ps[row * 4 + wn] = psum[mt][rs];
                }
        }

        // O rescale
#pragma unroll
        for (int mt = 0; mt < 2; ++mt) {
            float f0 = fsc[mt][0], f1 = fsc[mt][1];
#pragma unroll
            for (int nt = 0; nt < 4; ++nt) {
                O[mt * 4 + nt][0] *= f0; O[mt * 4 + nt][1] *= f0;
                O[mt * 4 + nt][2] *= f1; O[mt * 4 + nt][3] *= f1;
            }
        }
        __syncthreads();   // B: P, ps, V, K-next visible; mold reads done

        // designated m/l update
        if (wn == 0 && (lane & 3) == 0) {
#pragma unroll
            for (int mt = 0; mt < 2; ++mt)
#pragma unroll
                for (int rs = 0; rs < 2; ++rs) {
                    int row = wm * 32 + mt * 16 + (lane >> 2) + rs * 8;
                    float4 s4 = *(float4*)&ps[row * 4];
                    l_s[row] = l_s[row] * fsc[mt][rs] + (s4.x + s4.y + s4.z + s4.w);
                    m_s[row] = mnew[mt][rs];
                }
        }

        // O += P @ V
#pragma unroll
        for (int ks = 0; ks < 4; ++ks) {
            const int kb = ks * 16;
            uint32_t af[2][4], bf[4][2];
#pragma unroll
            for (int mt = 0; mt < 2; ++mt) {
                uint32_t addr = Sa + (wm * 32 + mt * 16 + a_row) * (SST_H * 2) + ks * 32 + a_kb;
                ldsm_x4(af[mt][0], af[mt][1], af[mt][2], af[mt][3], addr);
            }
#pragma unroll
            for (int p = 0; p < 2; ++p) {
                int c0 = wn * 32 + p * 16;
                uint32_t addr = Va + (kb + v_krow) * (TST_H * 2) + (c0 + v_noff) * 2;
                ldsm_x4_t(bf[2*p][0], bf[2*p][1], bf[2*p+1][0], bf[2*p+1][1], addr);
            }
#pragma unroll
            for (int mt = 0; mt < 2; ++mt)
#pragma unroll
                for (int nt = 0; nt < 4; ++nt)
                    mma_f16(O[mt * 4 + nt],
                            af[mt][0], af[mt][1], af[mt][2], af[mt][3],
                            bf[nt][0], bf[nt][1]);
        }
    }

    __syncthreads();   // last l_s/m_s updates visible

    // finalize -> fp16 g_ot
#pragma unroll
    for (int mt = 0; mt < 2; ++mt) {
        int r = wm * 32 + mt * 16 + (lane >> 2);
        float inv0 = 1.f / l_s[r], inv1 = 1.f / l_s[r + 8];
#pragma unroll
        for (int nt = 0; nt < 4; ++nt) {
            int c = wn * 32 + nt * 8 + (lane & 3) * 2;
            float* a4 = O[mt * 4 + nt];
            *(__half2*)(g_ot + (size_t)(q0 + r) * DIM + h * HD + c) =
                __floats2half2_rn(a4[0] * inv0, a4[1] * inv0);
            *(__half2*)(g_ot + (size_t)(q0 + r + 8) * DIM + h * HD + c) =
                __floats2half2_rn(a4[2] * inv1, a4[3] * inv1);
        }
    }
}

// ================= launch =================
extern "C" void kernel_launch(void* const* d_in, const int* in_sizes, int n_in,
                              void* d_out, int out_size)
{
    const float* x          = (const float*)d_in[0];
    const int*   grid_sizes = (const int*)d_in[2];
    const float* freqs      = (const float*)d_in[3];
    const float* Wq = (const float*)d_in[4];
    const float* bq = (const float*)d_in[5];
    const float* Wk = (const float*)d_in[6];
    const float* bk = (const float*)d_in[7];
    const float* Wv = (const float*)d_in[8];
    const float* bv = (const float*)d_in[9];
    const float* Wo = (const float*)d_in[10];
    const float* bo = (const float*)d_in[11];
    const float* gq = (const float*)d_in[12];
    const float* gk = (const float*)d_in[13];
    float* out = (float*)d_out;

    __half *xt, *wt;
    float *qp, *kp;
    cudaGetSymbolAddress((void**)&xt, g_xt);
    cudaGetSymbolAddress((void**)&wt, g_wt);
    cudaGetSymbolAddress((void**)&qp, g_q);
    cudaGetSymbolAddress((void**)&kp, g_k);

    cudaFuncSetAttribute(flash_f16, cudaFuncAttributeMaxDynamicSharedMemorySize, FLASH_SMEM_BYTES);
    cudaFuncSetAttribute(qkv_gemm_f16, cudaFuncAttributeMaxDynamicSharedMemorySize, GM_SMEM_BYTES);
    cudaFuncSetAttribute(out_gemm_f16, cudaFuncAttributeMaxDynamicSharedMemorySize, GM_SMEM_BYTES);

    const int NX4 = LTOK * DIM / 4;
    const int NW4 = DIM * DIM / 4;

    convert_f16<<<(NX4 + 255) / 256, 256>>>((const float4*)x,  (uint2*)xt, NX4);
    convert_f16<<<(NW4 + 255) / 256, 256>>>((const float4*)Wq, (uint2*)(wt + 0 * (size_t)DIM * DIM), NW4);
    convert_f16<<<(NW4 + 255) / 256, 256>>>((const float4*)Wk, (uint2*)(wt + 1 * (size_t)DIM * DIM), NW4);
    convert_f16<<<(NW4 + 255) / 256, 256>>>((const float4*)Wv, (uint2*)(wt + 2 * (size_t)DIM * DIM), NW4);
    convert_f16<<<(NW4 + 255) / 256, 256>>>((const float4*)Wo, (uint2*)(wt + 3 * (size_t)DIM * DIM), NW4);

    dim3 gqkv(DIM / GM_BN, (LTOK + GM_BM - 1) / GM_BM, 3);   // 12 x 28 x 3
    dim3 gout(DIM / GM_BN, (LTOK + GM_BM - 1) / GM_BM, 2);   // 12 x 28 x 2 (split-K)

    qkv_gemm_f16<<<gqkv, 256, GM_SMEM_BYTES>>>(bq, bk, bv);
    rmsnorm_rope<<<dim3(LTOK, 2), 256>>>(gq, gk, freqs, grid_sizes);
    flash_f16<<<dim3(LTOK / FQ, HEADS), 256, FLASH_SMEM_BYTES>>>();
    out_gemm_f16<<<gout, 256, GM_SMEM_BYTES>>>();
    reduce_bias<<<(NX4 + 255) / 256, 256>>>((const float4*)qp, (const float4*)kp,
                                            (const float4*)bo, (float4*)out, NX4);
}

// round 15
// speedup vs baseline: 2.0992x; 1.0221x over previous
#include <cuda_runtime.h>
#include <cuda_fp16.h>
#include <cstdint>

#define DIM    1536
#define HEADS  12
#define HD     128
#define LTOK   3520
#define EPS    1e-6f
#define SCALE  0.08838834764831845f   // 1/sqrt(128)
#define LOG2E  1.4426950408889634f

// ---------------- scratch (no allocation allowed) ----------------
__device__ float  g_p0[LTOK * DIM];   // split-K out partial 0
__device__ float  g_p1[LTOK * DIM];   // split-K out partial 1
__device__ __half g_xt[LTOK * DIM];
__device__ __half g_wt[4][DIM * DIM];
__device__ __half g_qh[LTOK * DIM];   // raw q (fp16, from gemm)
__device__ __half g_kh[LTOK * DIM];   // raw k
__device__ __half g_qt[LTOK * DIM];   // rmsnorm+rope q, *SCALE*log2e
__device__ __half g_kt[LTOK * DIM];   // rmsnorm+rope k
__device__ __half g_vt[LTOK * DIM];   // v
__device__ __half g_ot[LTOK * DIM];   // attention output

// ---------------- helpers ----------------
__device__ __forceinline__ void mma_f16(float c[4],
    uint32_t a0, uint32_t a1, uint32_t a2, uint32_t a3,
    uint32_t b0, uint32_t b1)
{
    asm volatile(
        "mma.sync.aligned.m16n8k16.row.col.f32.f16.f16.f32 "
        "{%0,%1,%2,%3}, {%4,%5,%6,%7}, {%8,%9}, {%0,%1,%2,%3};\n"
        : "+f"(c[0]), "+f"(c[1]), "+f"(c[2]), "+f"(c[3])
        : "r"(a0), "r"(a1), "r"(a2), "r"(a3), "r"(b0), "r"(b1));
}
__device__ __forceinline__ void ldsm_x4(uint32_t& r0, uint32_t& r1,
                                        uint32_t& r2, uint32_t& r3, uint32_t addr)
{
    asm volatile("ldmatrix.sync.aligned.m8n8.x4.shared.b16 {%0,%1,%2,%3}, [%4];"
                 : "=r"(r0), "=r"(r1), "=r"(r2), "=r"(r3) : "r"(addr));
}
__device__ __forceinline__ void ldsm_x4_t(uint32_t& r0, uint32_t& r1,
                                          uint32_t& r2, uint32_t& r3, uint32_t addr)
{
    asm volatile("ldmatrix.sync.aligned.m8n8.x4.trans.shared.b16 {%0,%1,%2,%3}, [%4];"
                 : "=r"(r0), "=r"(r1), "=r"(r2), "=r"(r3) : "r"(addr));
}
__device__ __forceinline__ uint32_t smem_addr(const void* p) {
    return (uint32_t)__cvta_generic_to_shared(p);
}
__device__ __forceinline__ void cp_async16(uint32_t dst, const void* src) {
    asm volatile("cp.async.cg.shared.global [%0], [%1], 16;" :: "r"(dst), "l"(src));
}
#define CP_COMMIT() asm volatile("cp.async.commit_group;" ::: "memory")
#define CP_WAIT1()  asm volatile("cp.async.wait_group 1;" ::: "memory")

__device__ __forceinline__ uint32_t h2exp2(uint32_t x) {
    uint32_t r;
    asm("ex2.approx.f16x2 %0, %1;" : "=r"(r) : "r"(x));
    return r;
}

// ================= converts =================
__global__ void __launch_bounds__(256) convert_f16(const float4* __restrict__ src,
                                                   uint2* __restrict__ dst, int n4)
{
    int i = blockIdx.x * blockDim.x + threadIdx.x;
    if (i < n4) {
        float4 v = src[i];
        __half2 lo = __floats2half2_rn(v.x, v.y);
        __half2 hi = __floats2half2_rn(v.z, v.w);
        dst[i] = make_uint2(*(uint32_t*)&lo, *(uint32_t*)&hi);
    }
}

__global__ void __launch_bounds__(256) convert_w4(
    const float4* __restrict__ Wq, const float4* __restrict__ Wk,
    const float4* __restrict__ Wv, const float4* __restrict__ Wo,
    uint2* __restrict__ dst, int nw4)
{
    int i = blockIdx.x * blockDim.x + threadIdx.x;
    if (i >= 4 * nw4) return;
    int w = i / nw4, j = i - w * nw4;
    const float4* src = (w == 0) ? Wq : (w == 1) ? Wk : (w == 2) ? Wv : Wo;
    float4 v = src[j];
    __half2 lo = __floats2half2_rn(v.x, v.y);
    __half2 hi = __floats2half2_rn(v.z, v.w);
    dst[i] = make_uint2(*(uint32_t*)&lo, *(uint32_t*)&hi);
}

// ============ reduce: out = p0 + p1 + bias =============================
__global__ void __launch_bounds__(256) reduce_bias(
    const float4* __restrict__ p0, const float4* __restrict__ p1,
    const float4* __restrict__ bias, float4* __restrict__ out, int n4)
{
    int i = blockIdx.x * blockDim.x + threadIdx.x;
    if (i < n4) {
        float4 a = p0[i], b = p1[i], bb = bias[i % (DIM / 4)];
        out[i] = make_float4(a.x + b.x + bb.x, a.y + b.y + bb.y,
                             a.z + b.z + bb.z, a.w + b.w + bb.w);
    }
}

// ================= fp16 GEMM core =================
#define GM_BM 128
#define GM_BN 128
#define GM_BK 64
#define GSTR_H 72
#define GM_TILE_H (GM_BM * GSTR_H)
#define GM_STAGE_H (2 * GM_TILE_H)
#define GM_SMEM_BYTES (3 * GM_STAGE_H * 2)   // 110592

__device__ __forceinline__ void gemm_tile_f16(
    const __half* __restrict__ A, const __half* __restrict__ B,
    const float* __restrict__ bias, float* __restrict__ Cf, __half* __restrict__ Ch,
    int M, int N, int K, int kbeg, int klen, int m0, int n0, __half* sm)
{
    const int tid = threadIdx.x;
    const int lane = tid & 31;
    const int wid = tid >> 5;
    const int wm = wid >> 2;
    const int wn = wid & 3;

    const int tr = lane & 7;
    const int mq = lane >> 3;
    const int a_row = tr + 8 * (mq & 1);
    const int a_kb  = 16 * (mq >> 1);
    const int b_row = tr + 8 * (mq >> 1);
    const int b_kb  = 16 * (mq & 1);

    int r2[4], kc2[4], arow[4], brow[4];
#pragma unroll
    for (int i = 0; i < 4; ++i) {
        int s = tid + i * 256;
        r2[i] = s >> 3;
        kc2[i] = (s & 7) * 8;
        arow[i] = min(m0 + r2[i], M - 1);
        brow[i] = n0 + r2[i];
    }

    const uint32_t smu = smem_addr(sm);

    auto fill = [&](int st, int k0) {
        const uint32_t base = smu + 2u * (st * GM_STAGE_H);
#pragma unroll
        for (int i = 0; i < 4; ++i)
            cp_async16(base + 2u * (r2[i] * GSTR_H + kc2[i]),
                       A + (size_t)arow[i] * K + k0 + kc2[i]);
#pragma unroll
        for (int i = 0; i < 4; ++i)
            cp_async16(base + 2u * (GM_TILE_H + r2[i] * GSTR_H + kc2[i]),
                       B + (size_t)brow[i] * K + k0 + kc2[i]);
        CP_COMMIT();
    };

    fill(0, kbeg);
    fill(1, kbeg + GM_BK);

    float acc[16][4];
#pragma unroll
    for (int t = 0; t < 16; ++t)
        acc[t][0] = acc[t][1] = acc[t][2] = acc[t][3] = 0.f;

    const int NIT = klen / GM_BK;
    int st = 0;
    for (int it = 0; it < NIT; ++it) {
        CP_WAIT1();
        __syncthreads();
        if (it + 2 < NIT) fill((st + 2) % 3, kbeg + (it + 2) * GM_BK);
        else CP_COMMIT();

        const uint32_t Ab = smu + 2u * (st * GM_STAGE_H);
        const uint32_t Bb = Ab + 2u * GM_TILE_H;
#pragma unroll
        for (int ks = 0; ks < 4; ++ks) {
            const int kbb = ks * 32;
            uint32_t af[4][4], bf[4][2];
#pragma unroll
            for (int mt = 0; mt < 4; ++mt) {
                uint32_t addr = Ab + (wm * 64 + mt * 16 + a_row) * (GSTR_H * 2) + kbb + a_kb;
                ldsm_x4(af[mt][0], af[mt][1], af[mt][2], af[mt][3], addr);
            }
#pragma unroll
            for (int p = 0; p < 2; ++p) {
                uint32_t addr = Bb + (wn * 32 + p * 16 + b_row) * (GSTR_H * 2) + kbb + b_kb;
                ldsm_x4(bf[2*p][0], bf[2*p][1], bf[2*p+1][0], bf[2*p+1][1], addr);
            }
#pragma unroll
            for (int mt = 0; mt < 4; ++mt)
#pragma unroll
                for (int nt = 0; nt < 4; ++nt)
                    mma_f16(acc[mt * 4 + nt],
                            af[mt][0], af[mt][1], af[mt][2], af[mt][3],
                            bf[nt][0], bf[nt][1]);
        }
        st = (st + 1) % 3;
    }

    // epilogue
#pragma unroll
    for (int nt = 0; nt < 4; ++nt) {
        int c = n0 + wn * 32 + nt * 8 + (lane & 3) * 2;
        float b0 = 0.f, b1 = 0.f;
        if (bias) { b0 = bias[c]; b1 = bias[c + 1]; }
#pragma unroll
        for (int mt = 0; mt < 4; ++mt) {
            int r = m0 + wm * 64 + mt * 16 + (lane >> 2);
            float* a4 = acc[mt * 4 + nt];
            if (Ch) {
                if (r < M)
                    *(__half2*)(Ch + (size_t)r * N + c) = __floats2half2_rn(a4[0] + b0, a4[1] + b1);
                if (r + 8 < M)
                    *(__half2*)(Ch + (size_t)(r + 8) * N + c) = __floats2half2_rn(a4[2] + b0, a4[3] + b1);
            } else {
                if (r < M)
                    *(float2*)(Cf + (size_t)r * N + c) = make_float2(a4[0] + b0, a4[1] + b1);
                if (r + 8 < M)
                    *(float2*)(Cf + (size_t)(r + 8) * N + c) = make_float2(a4[2] + b0, a4[3] + b1);
            }
        }
    }
}

__global__ void __launch_bounds__(256, 2) qkv_gemm_f16(
    const float* __restrict__ bq, const float* __restrict__ bk,
    const float* __restrict__ bv)
{
    extern __shared__ __align__(16) __half smh[];
    const float* b; __half* outH;
    if (blockIdx.z == 0)      { b = bq; outH = g_qh; }
    else if (blockIdx.z == 1) { b = bk; outH = g_kh; }
    else                      { b = bv; outH = g_vt; }
    gemm_tile_f16(g_xt, g_wt[blockIdx.z], b, nullptr, outH, LTOK, DIM, DIM,
                  0, DIM, blockIdx.y * GM_BM, blockIdx.x * GM_BN, smh);
}

__global__ void __launch_bounds__(256, 2) out_gemm_f16()
{
    extern __shared__ __align__(16) __half smh[];
    float* part = blockIdx.z ? g_p1 : g_p0;
    gemm_tile_f16(g_ot, g_wt[3], nullptr, part, nullptr, LTOK, DIM, DIM,
                  blockIdx.z * (DIM / 2), DIM / 2,
                  blockIdx.y * GM_BM, blockIdx.x * GM_BN, smh);
}

// ============ fused RMSNorm + RoPE (fp16 in/out, q pre-scaled) ===========
__global__ void __launch_bounds__(256) rmsnorm_rope(
    const float* __restrict__ gq, const float* __restrict__ gk,
    const float* __restrict__ freqs, const int* __restrict__ gsz)
{
    const int t = blockIdx.x;
    const int which = blockIdx.y;
    const __half* row = (which ? g_kh : g_qh) + (size_t)t * DIM;
    __half* rowo = (which ? g_kt : g_qt) + (size_t)t * DIM;
    const float oscale = which ? 1.0f : (SCALE * LOG2E);
    const float* g = which ? gk : gq;
    const int tid = threadIdx.x;

    float ss = 0.f;
    for (int i = tid; i < DIM / 2; i += 256) {
        float2 v = __half22float2(((const __half2*)row)[i]);
        ss += v.x * v.x + v.y * v.y;
    }
    __shared__ float red[8];
#pragma unroll
    for (int o = 16; o; o >>= 1) ss += __shfl_xor_sync(0xffffffffu, ss, o);
    if ((tid & 31) == 0) red[tid >> 5] = ss;
    __syncthreads();
    if (tid < 8) {
        float v = red[tid];
#pragma unroll
        for (int o = 4; o; o >>= 1) v += __shfl_xor_sync(0xffu, v, o);
        if (tid == 0) red[0] = v;
    }
    __syncthreads();
    const float rms = rsqrtf(red[0] * (1.0f / DIM) + EPS);

    const int Hs = gsz[1], Ws = gsz[2];
    const int fi = t / (Hs * Ws);
    const int hi = (t / Ws) % Hs;
    const int wi = t % Ws;

    for (int p = tid; p < HEADS * 64; p += 256) {
        const int h = p >> 6;
        const int j = p & 63;
        const int pos = (j < 22) ? fi : ((j < 43) ? hi : wi);
        const float ang = freqs[pos * 64 + j];
        float c, s;
        sincosf(ang, &s, &c);
        const int d0 = h * HD + 2 * j;
        float2 xv = __half22float2(*(const __half2*)(row + d0));
        const float x0 = xv.x * rms * g[d0];
        const float x1 = xv.y * rms * g[d0 + 1];
        __half2 o = __floats2half2_rn((x0 * c - x1 * s) * oscale,
                                      (x0 * s + x1 * c) * oscale);
        *(__half2*)(rowo + d0) = o;
    }
}

// ====== flash attention: fp16 mma, K dbl-buffer + V buffer, f16x2 exp2 ==
#define FQ 64
#define FK 64
#define TST_H 136
#define SST_H 72
#define FLASH_SMEM_BYTES (4*FQ*TST_H*2 + FQ*SST_H*2 + (2*FQ + 8*FQ)*4)

__global__ void __launch_bounds__(256, 2) flash_f16()
{
    extern __shared__ __align__(16) char smc[];
    __half* Qs = (__half*)smc;
    __half* K0 = Qs + FQ * TST_H;
    __half* K1 = K0 + FQ * TST_H;
    __half* Vs = K1 + FQ * TST_H;
    __half* Ss = Vs + FQ * TST_H;
    float* m_s = (float*)(Ss + FQ * SST_H);
    float* l_s = m_s + FQ;
    float* pm  = l_s + FQ;          // [64][4]
    float* ps  = pm + FQ * 4;       // [64][4]

    const int tid = threadIdx.x;
    const int lane = tid & 31;
    const int wid = tid >> 5;
    const int wm = wid >> 2;
    const int wn = wid & 3;
    const int h  = blockIdx.y;
    const int q0 = blockIdx.x * FQ;

    const int tr = lane & 7;
    const int mq = lane >> 3;
    const int a_row = tr + 8 * (mq & 1);
    const int a_kb  = 16 * (mq >> 1);
    const int b_row = tr + 8 * (mq >> 1);
    const int b_kb  = 16 * (mq & 1);
    const int v_krow = tr + 8 * (mq & 1);
    const int v_noff = 8 * (mq >> 1);

    const uint32_t Qa = smem_addr(Qs);
    const uint32_t K0a = smem_addr(K0);
    const uint32_t K1a = smem_addr(K1);
    const uint32_t Va = smem_addr(Vs);
    const uint32_t Sa = smem_addr(Ss);

    int srow[4], scol[4];
#pragma unroll
    for (int j = 0; j < 4; ++j) {
        int i = tid + j * 256;
        srow[j] = i >> 4;
        scol[j] = (i & 15) * 8;
    }

    // Q tile + K(0)
#pragma unroll
    for (int j = 0; j < 4; ++j) {
        uint4 v = *(const uint4*)(g_qt + (size_t)(q0 + srow[j]) * DIM + h * HD + scol[j]);
        *(uint4*)&Qs[srow[j] * TST_H + scol[j]] = v;
        uint4 kv = *(const uint4*)(g_kt + (size_t)srow[j] * DIM + h * HD + scol[j]);
        *(uint4*)&K0[srow[j] * TST_H + scol[j]] = kv;
    }
    if (tid < FQ) { m_s[tid] = -3.0e38f; l_s[tid] = 0.f; }

    float O[8][4];
#pragma unroll
    for (int t = 0; t < 8; ++t) O[t][0] = O[t][1] = O[t][2] = O[t][3] = 0.f;

    __syncthreads();

    int it = 0;
    for (int t0 = 0; t0 < LTOK; t0 += FK, ++it) {
        const uint32_t Kcur = (it & 1) ? K1a : K0a;
        __half* Knext = (it & 1) ? K0 : K1;

        uint4 vreg[4], kreg[4];
#pragma unroll
        for (int j = 0; j < 4; ++j)
            vreg[j] = *(const uint4*)(g_vt + (size_t)(t0 + srow[j]) * DIM + h * HD + scol[j]);
        const bool has_next = (t0 + FK < LTOK);
        if (has_next) {
#pragma unroll
            for (int j = 0; j < 4; ++j)
                kreg[j] = *(const uint4*)(g_kt + (size_t)(t0 + FK + srow[j]) * DIM + h * HD + scol[j]);
        }

        // S = Q K^T (log2-domain, fp32 accum)
        float Sacc[2][2][4] = {};
#pragma unroll
        for (int ks = 0; ks < 8; ++ks) {
            const int kbb = ks * 32;
            uint32_t af[2][4], bf[2][2];
#pragma unroll
            for (int mt = 0; mt < 2; ++mt) {
                uint32_t addr = Qa + (wm * 32 + mt * 16 + a_row) * (TST_H * 2) + kbb + a_kb;
                ldsm_x4(af[mt][0], af[mt][1], af[mt][2], af[mt][3], addr);
            }
            {
                uint32_t addr = Kcur + (wn * 16 + b_row) * (TST_H * 2) + kbb + b_kb;
                ldsm_x4(bf[0][0], bf[0][1], bf[1][0], bf[1][1], addr);
            }
#pragma unroll
            for (int mt = 0; mt < 2; ++mt)
#pragma unroll
                for (int nt = 0; nt < 2; ++nt)
                    mma_f16(Sacc[mt][nt],
                            af[mt][0], af[mt][1], af[mt][2], af[mt][3],
                            bf[nt][0], bf[nt][1]);
        }

        // warp-partial row max
        float pmax[2][2];
#pragma unroll
        for (int mt = 0; mt < 2; ++mt) {
            pmax[mt][0] = fmaxf(fmaxf(Sacc[mt][0][0], Sacc[mt][0][1]),
                                fmaxf(Sacc[mt][1][0], Sacc[mt][1][1]));
            pmax[mt][1] = fmaxf(fmaxf(Sacc[mt][0][2], Sacc[mt][0][3]),
                                fmaxf(Sacc[mt][1][2], Sacc[mt][1][3]));
#pragma unroll
            for (int rs = 0; rs < 2; ++rs) {
                pmax[mt][rs] = fmaxf(pmax[mt][rs], __shfl_xor_sync(0xffffffffu, pmax[mt][rs], 1));
                pmax[mt][rs] = fmaxf(pmax[mt][rs], __shfl_xor_sync(0xffffffffu, pmax[mt][rs], 2));
            }
        }
        if ((lane & 3) == 0) {
#pragma unroll
            for (int mt = 0; mt < 2; ++mt)
#pragma unroll
                for (int rs = 0; rs < 2; ++rs) {
                    int row = wm * 32 + mt * 16 + (lane >> 2) + rs * 8;
                    pm[row * 4 + wn] = pmax[mt][rs];
                }
        }
        __syncthreads();   // A

        // commit V(t), K(t+1)
#pragma unroll
        for (int j = 0; j < 4; ++j)
            *(uint4*)&Vs[srow[j] * TST_H + scol[j]] = vreg[j];
        if (has_next) {
#pragma unroll
            for (int j = 0; j < 4; ++j)
                *(uint4*)&Knext[srow[j] * TST_H + scol[j]] = kreg[j];
        }

        // softmax: mnew, f, P via ex2.f16x2
        float mnew[2][2], fsc[2][2], psum[2][2];
#pragma unroll
        for (int mt = 0; mt < 2; ++mt)
#pragma unroll
            for (int rs = 0; rs < 2; ++rs) {
                int row = wm * 32 + mt * 16 + (lane >> 2) + rs * 8;
                float4 pv = *(float4*)&pm[row * 4];
                float mold = m_s[row];
                float mx = fmaxf(fmaxf(pv.x, pv.y), fmaxf(pv.z, pv.w));
                float mn = fmaxf(mold, mx);
                mnew[mt][rs] = mn;
                fsc[mt][rs] = exp2f(mold - mn);
                psum[mt][rs] = 0.f;
            }
#pragma unroll
        for (int mt = 0; mt < 2; ++mt) {
            int r = wm * 32 + mt * 16 + (lane >> 2);
            int c = wn * 16 + (lane & 3) * 2;
#pragma unroll
            for (int nt = 0; nt < 2; ++nt) {
                __half2 s0 = __floats2half2_rn(Sacc[mt][nt][0] - mnew[mt][0],
                                               Sacc[mt][nt][1] - mnew[mt][0]);
                __half2 s1 = __floats2half2_rn(Sacc[mt][nt][2] - mnew[mt][1],
                                               Sacc[mt][nt][3] - mnew[mt][1]);
                uint32_t p0 = h2exp2(*(uint32_t*)&s0);
                uint32_t p1 = h2exp2(*(uint32_t*)&s1);
                *(uint32_t*)&Ss[r * SST_H + c + nt * 8] = p0;
                *(uint32_t*)&Ss[(r + 8) * SST_H + c + nt * 8] = p1;
                float2 f0 = __half22float2(*(__half2*)&p0);
                float2 f1 = __half22float2(*(__half2*)&p1);
                psum[mt][0] += f0.x + f0.y;
                psum[mt][1] += f1.x + f1.y;
            }
        }
#pragma unroll
        for (int mt = 0; mt < 2; ++mt)
#pragma unroll
            for (int rs = 0; rs < 2; ++rs) {
                psum[mt][rs] += __shfl_xor_sync(0xffffffffu, psum[mt][rs], 1);
                psum[mt][rs] += __shfl_xor_sync(0xffffffffu, psum[mt][rs], 2);
            }
        if ((lane & 3) == 0) {
#pragma unroll
            for (int mt = 0; mt < 2; ++mt)
#pragma unroll
                for (int rs = 0; rs < 2; ++rs) {
                    int row = wm * 32 + mt * 16 + (lane >> 2) + rs * 8;
                    ps[row * 4 + wn] = psum[mt][rs];
                }
        }

        // O rescale
#pragma unroll
        for (int mt = 0; mt < 2; ++mt) {
            float f0 = fsc[mt][0], f1 = fsc[mt][1];
#pragma unroll
            for (int nt = 0; nt < 4; ++nt) {
                O[mt * 4 + nt][0] *= f0; O[mt * 4 + nt][1] *= f0;
                O[mt * 4 + nt][2] *= f1; O[mt * 4 + nt][3] *= f1;
            }
        }
        __syncthreads();   // B

        if (wn == 0 && (lane & 3) == 0) {
#pragma unroll
            for (int mt = 0; mt < 2; ++mt)
#pragma unroll
                for (int rs = 0; rs < 2; ++rs) {
                    int row = wm * 32 + mt * 16 + (lane >> 2) + rs * 8;
                    float4 s4 = *(float4*)&ps[row * 4];
                    l_s[row] = l_s[row] * fsc[mt][rs] + (s4.x + s4.y + s4.z + s4.w);
                    m_s[row] = mnew[mt][rs];
                }
        }

        // O += P @ V
#pragma unroll
        for (int ks = 0; ks < 4; ++ks) {
            const int kb = ks * 16;
            uint32_t af[2][4], bf[4][2];
#pragma unroll
            for (int mt = 0; mt < 2; ++mt) {
                uint32_t addr = Sa + (wm * 32 + mt * 16 + a_row) * (SST_H * 2) + ks * 32 + a_kb;
                ldsm_x4(af[mt][0], af[mt][1], af[mt][2], af[mt][3], addr);
            }
#pragma unroll
            for (int p = 0; p < 2; ++p) {
                int c0 = wn * 32 + p * 16;
                uint32_t addr = Va + (kb + v_krow) * (TST_H * 2) + (c0 + v_noff) * 2;
                ldsm_x4_t(bf[2*p][0], bf[2*p][1], bf[2*p+1][0], bf[2*p+1][1], addr);
            }
#pragma unroll
            for (int mt = 0; mt < 2; ++mt)
#pragma unroll
                for (int nt = 0; nt < 4; ++nt)
                    mma_f16(O[mt * 4 + nt],
                            af[mt][0], af[mt][1], af[mt][2], af[mt][3],
                            bf[nt][0], bf[nt][1]);
        }
    }

    __syncthreads();

    // finalize -> fp16 g_ot
#pragma unroll
    for (int mt = 0; mt < 2; ++mt) {
        int r = wm * 32 + mt * 16 + (lane >> 2);
        float inv0 = 1.f / l_s[r], inv1 = 1.f / l_s[r + 8];
#pragma unroll
        for (int nt = 0; nt < 4; ++nt) {
            int c = wn * 32 + nt * 8 + (lane & 3) * 2;
            float* a4 = O[mt * 4 + nt];
            *(__half2*)(g_ot + (size_t)(q0 + r) * DIM + h * HD + c) =
                __floats2half2_rn(a4[0] * inv0, a4[1] * inv0);
            *(__half2*)(g_ot + (size_t)(q0 + r + 8) * DIM + h * HD + c) =
                __floats2half2_rn(a4[2] * inv1, a4[3] * inv1);
        }
    }
}

// ================= launch =================
extern "C" void kernel_launch(void* const* d_in, const int* in_sizes, int n_in,
                              void* d_out, int out_size)
{
    const float* x          = (const float*)d_in[0];
    const int*   grid_sizes = (const int*)d_in[2];
    const float* freqs      = (const float*)d_in[3];
    const float* Wq = (const float*)d_in[4];
    const float* bq = (const float*)d_in[5];
    const float* Wk = (const float*)d_in[6];
    const float* bk = (const float*)d_in[7];
    const float* Wv = (const float*)d_in[8];
    const float* bv = (const float*)d_in[9];
    const float* Wo = (const float*)d_in[10];
    const float* bo = (const float*)d_in[11];
    const float* gq = (const float*)d_in[12];
    const float* gk = (const float*)d_in[13];
    float* out = (float*)d_out;

    __half *xt, *wt;
    float *p0, *p1;
    cudaGetSymbolAddress((void**)&xt, g_xt);
    cudaGetSymbolAddress((void**)&wt, g_wt);
    cudaGetSymbolAddress((void**)&p0, g_p0);
    cudaGetSymbolAddress((void**)&p1, g_p1);

    cudaFuncSetAttribute(flash_f16, cudaFuncAttributeMaxDynamicSharedMemorySize, FLASH_SMEM_BYTES);
    cudaFuncSetAttribute(qkv_gemm_f16, cudaFuncAttributeMaxDynamicSharedMemorySize, GM_SMEM_BYTES);
    cudaFuncSetAttribute(out_gemm_f16, cudaFuncAttributeMaxDynamicSharedMemorySize, GM_SMEM_BYTES);

    const int NX4 = LTOK * DIM / 4;
    const int NW4 = DIM * DIM / 4;

    convert_f16<<<(NX4 + 255) / 256, 256>>>((const float4*)x, (uint2*)xt, NX4);
    convert_w4<<<(4 * NW4 + 255) / 256, 256>>>((const float4*)Wq, (const float4*)Wk,
                                               (const float4*)Wv, (const float4*)Wo,
                                               (uint2*)wt, NW4);

    dim3 gqkv(DIM / GM_BN, (LTOK + GM_BM - 1) / GM_BM, 3);
    dim3 gout(DIM / GM_BN, (LTOK + GM_BM - 1) / GM_BM, 2);

    qkv_gemm_f16<<<gqkv, 256, GM_SMEM_BYTES>>>(bq, bk, bv);
    rmsnorm_rope<<<dim3(LTOK, 2), 256>>>(gq, gk, freqs, grid_sizes);
    flash_f16<<<dim3(LTOK / FQ, HEADS), 256, FLASH_SMEM_BYTES>>>();
    out_gemm_f16<<<gout, 256, GM_SMEM_BYTES>>>();
    reduce_bias<<<(NX4 + 255) / 256, 256>>>((const float4*)p0, (const float4*)p1,
                                            (const float4*)bo, (float4*)out, NX4);
}